// round 3
// baseline (speedup 1.0000x reference)
#include <cuda_runtime.h>
#include <cuda_bf16.h>
#include <math.h>

// ---------------------------------------------------------------------------
//   x: (8,16,3,84,84)  B=8 T=16  -> BT=128 frames
//   enc: 3->64 (pool), 64->128 (pool), 128->256    @84/42/21
//   ConvLSTM: depthwise 3x3 g=512, pointwise 512->1024, gates
//   dec: up2 conv 256->128 @42, up2 conv 128->64 @84, 1x1 64->1
//   outputs: out (8,16,1,84,84), h (8,256,21,21), c (8,256,21,21)
// ---------------------------------------------------------------------------

#define BT   128
#define BB   8
#define TT   16
#define HD   256
#define NP2  441
#define NP1  1764
#define NP0  7056
#define OUTN 903168

__device__ float g_e1 [BT * 64  * NP1];
__device__ float g_e2 [BT * 128 * NP2];
__device__ float g_feat[BT * 256 * NP2];
__device__ float g_gdw[BB * 512 * NP2];
__device__ float g_hs [BT * 256 * NP2];
__device__ float g_d1 [BT * 128 * NP1];
__device__ float g_d2 [BT * 64  * NP0];
__device__ float g_h  [BB * HD * NP2];
__device__ float g_c  [BB * HD * NP2];

__device__ __forceinline__ float sigm(float x) { return 1.0f / (1.0f + expf(-x)); }

__global__ void k_zero_hc()
{
    int i = blockIdx.x * blockDim.x + threadIdx.x;
    if (i < BB * HD * NP2) { g_h[i] = 0.0f; g_c[i] = 0.0f; }
}

// ---------------------------------------------------------------------------
// enc1: conv3x3 3->64 + bias + relu + maxpool2.  84x84 -> pooled 42x42
// (small layer; unchanged from passing round-2 version)
// ---------------------------------------------------------------------------
__global__ void __launch_bounds__(448) k_enc1(
    const float* __restrict__ x, const float* __restrict__ w,
    const float* __restrict__ bias, float* __restrict__ out)
{
    __shared__ float s_in[3 * 44 * 44];
    __shared__ __align__(16) float s_w[3 * 9 * 64];

    const int n   = blockIdx.z;
    const int bx  = blockIdx.x;
    const int py0 = (bx >> 1) * 21;
    const int px0 = (bx & 1) * 21;
    const int oy0 = py0 * 2;
    const int ox0 = px0 * 2;
    const int tid = threadIdx.x;

    const float* xn = x + (size_t)n * 3 * NP0;

    for (int idx = tid; idx < 3 * 44 * 44; idx += 448) {
        int ci = idx / 1936, rem = idx % 1936;
        int r = rem / 44, c = rem % 44;
        int gy = oy0 - 1 + r, gx = ox0 - 1 + c;
        float v = 0.0f;
        if (gy >= 0 && gy < 84 && gx >= 0 && gx < 84)
            v = xn[(size_t)ci * NP0 + gy * 84 + gx];
        s_in[idx] = v;
    }
    for (int idx = tid; idx < 3 * 9 * 64; idx += 448) {
        int ci = idx / (9 * 64); int k = (idx % (9 * 64)) / 64; int co = idx % 64;
        s_w[idx] = w[((size_t)co * 3 + ci) * 9 + k];
    }
    __syncthreads();
    if (tid >= 441) return;

    const int ty = tid / 21, tx = tid % 21;
    const int by = 2 * ty, bxp = 2 * tx;

    for (int cg = 0; cg < 8; cg++) {
        float acc[8][4];
        #pragma unroll
        for (int j = 0; j < 8; j++) { acc[j][0]=acc[j][1]=acc[j][2]=acc[j][3]=0.f; }
        #pragma unroll
        for (int ci = 0; ci < 3; ci++) {
            const float* si = &s_in[ci * 1936];
            #pragma unroll
            for (int k = 0; k < 9; k++) {
                int dy = k / 3, dx = k % 3;
                const float* p0 = si + (by + dy) * 44 + (bxp + dx);
                float v00 = p0[0], v01 = p0[1], v10 = p0[44], v11 = p0[45];
                float4 wA = *(const float4*)&s_w[(ci * 9 + k) * 64 + cg * 8];
                float4 wB = *(const float4*)&s_w[(ci * 9 + k) * 64 + cg * 8 + 4];
                float wv[8] = {wA.x, wA.y, wA.z, wA.w, wB.x, wB.y, wB.z, wB.w};
                #pragma unroll
                for (int j = 0; j < 8; j++) {
                    acc[j][0] += v00 * wv[j];
                    acc[j][1] += v01 * wv[j];
                    acc[j][2] += v10 * wv[j];
                    acc[j][3] += v11 * wv[j];
                }
            }
        }
        #pragma unroll
        for (int j = 0; j < 8; j++) {
            int co = cg * 8 + j;
            float m = fmaxf(fmaxf(acc[j][0], acc[j][1]), fmaxf(acc[j][2], acc[j][3]));
            m = fmaxf(m + bias[co], 0.0f);
            out[(((size_t)n * 64 + co) * 42 + py0 + ty) * 42 + px0 + tx] = m;
        }
    }
}

// ---------------------------------------------------------------------------
// enc2: conv3x3 64->128 + bias + relu + maxpool2 @42 -> 21 (unchanged)
// ---------------------------------------------------------------------------
__global__ void __launch_bounds__(448) k_conv_pool(
    const float* __restrict__ in, const float* __restrict__ w,
    const float* __restrict__ bias, float* __restrict__ out,
    int Cin, int Cout, int Hc)
{
    const int CC = 4;
    __shared__ float s_in[CC * 44 * 44];
    __shared__ __align__(16) float s_w[CC * 9 * 8];

    const int n   = blockIdx.z;
    const int coB = blockIdx.y * 8;
    const int tid = threadIdx.x;
    const int ty = tid / 21, tx = tid % 21;
    const int by = 2 * ty, bxp = 2 * tx;

    float acc[8][4];
    #pragma unroll
    for (int j = 0; j < 8; j++) { acc[j][0]=acc[j][1]=acc[j][2]=acc[j][3]=0.f; }

    const float* inN = in + (size_t)n * Cin * Hc * Hc;

    for (int cc = 0; cc < Cin; cc += CC) {
        for (int idx = tid; idx < CC * 44 * 44; idx += 448) {
            int ci = idx / 1936, rem = idx % 1936;
            int r = rem / 44, c = rem % 44;
            int gy = r - 1, gx = c - 1;
            float v = 0.0f;
            if (gy >= 0 && gy < Hc && gx >= 0 && gx < Hc)
                v = inN[((size_t)(cc + ci) * Hc + gy) * Hc + gx];
            s_in[idx] = v;
        }
        for (int idx = tid; idx < CC * 9 * 8; idx += 448) {
            int ci = idx / 72; int k = (idx % 72) / 8; int co = idx % 8;
            s_w[idx] = w[((size_t)(coB + co) * Cin + (cc + ci)) * 9 + k];
        }
        __syncthreads();
        if (tid < 441) {
            #pragma unroll
            for (int ci = 0; ci < CC; ci++) {
                const float* si = &s_in[ci * 1936];
                #pragma unroll
                for (int k = 0; k < 9; k++) {
                    int dy = k / 3, dx = k % 3;
                    const float* p0 = si + (by + dy) * 44 + (bxp + dx);
                    float v00 = p0[0], v01 = p0[1], v10 = p0[44], v11 = p0[45];
                    float4 wA = *(const float4*)&s_w[(ci * 9 + k) * 8];
                    float4 wB = *(const float4*)&s_w[(ci * 9 + k) * 8 + 4];
                    float wv[8] = {wA.x, wA.y, wA.z, wA.w, wB.x, wB.y, wB.z, wB.w};
                    #pragma unroll
                    for (int j = 0; j < 8; j++) {
                        acc[j][0] += v00 * wv[j];
                        acc[j][1] += v01 * wv[j];
                        acc[j][2] += v10 * wv[j];
                        acc[j][3] += v11 * wv[j];
                    }
                }
            }
        }
        __syncthreads();
    }

    if (tid >= 441) return;
    int Hp = Hc >> 1;
    #pragma unroll
    for (int j = 0; j < 8; j++) {
        int co = coB + j;
        float m = fmaxf(fmaxf(acc[j][0], acc[j][1]), fmaxf(acc[j][2], acc[j][3]));
        m = fmaxf(m + bias[co], 0.0f);
        out[(((size_t)n * Cout + co) * Hp + ty) * Hp + tx] = m;
    }
}

// ---------------------------------------------------------------------------
// enc3: conv3x3 128->256 + bias + relu @21x21.
// 256 threads; thread = 2 adjacent pixels x 16 couts. Double-buffered smem.
// Per ci: 12 input LDS + 36 broadcast LDS.128 -> 288 FFMA.
// ---------------------------------------------------------------------------
__global__ void __launch_bounds__(256) k_enc3(
    const float* __restrict__ in, const float* __restrict__ w,
    const float* __restrict__ bias, float* __restrict__ out)
{
    const int CC = 8;
    __shared__ float s_in[2][CC * 529 + 8];
    __shared__ __align__(16) float s_w[2][CC * 9 * 16];

    const int coB = blockIdx.x * 16;
    const int n   = blockIdx.y;
    const int tid = threadIdx.x;
    const int y   = tid / 11;        // 0..20 for tid<231
    const int xp  = tid % 11;
    const int x0  = 2 * xp;
    const bool active = (tid < 231);
    const bool has2   = active && (xp < 10);

    float acc[2][16];
    #pragma unroll
    for (int p = 0; p < 2; p++)
        #pragma unroll
        for (int j = 0; j < 16; j++) acc[p][j] = 0.0f;

    const float* inN = in + (size_t)n * 128 * NP2;

    // fill buffer bb with channel chunk starting at cc
    auto fill = [&](int bb, int cc) {
        #pragma unroll 1
        for (int idx = tid; idx < CC * 529; idx += 256) {
            int ci = idx / 529, rem = idx % 529;
            int r = rem / 23, c = rem % 23;
            int gy = r - 1, gx = c - 1;
            float v = 0.0f;
            if (gy >= 0 && gy < 21 && gx >= 0 && gx < 21)
                v = inN[(size_t)(cc + ci) * NP2 + gy * 21 + gx];
            s_in[bb][idx] = v;
        }
        #pragma unroll 1
        for (int idx = tid; idx < CC * 144; idx += 256) {
            int ci = idx / 144; int k = (idx % 144) / 16; int co = idx % 16;
            s_w[bb][idx] = w[((size_t)(coB + co) * 128 + (cc + ci)) * 9 + k];
        }
    };

    fill(0, 0);
    __syncthreads();

    for (int it = 0; it < 16; it++) {
        int bb = it & 1;
        if (it + 1 < 16) fill(bb ^ 1, (it + 1) * CC);
        if (active) {
            #pragma unroll
            for (int ci = 0; ci < CC; ci++) {
                const float* si = &s_in[bb][ci * 529 + y * 23 + x0];
                float v[3][4];
                #pragma unroll
                for (int r = 0; r < 3; r++) {
                    v[r][0] = si[r*23+0]; v[r][1] = si[r*23+1];
                    v[r][2] = si[r*23+2]; v[r][3] = si[r*23+3];
                }
                #pragma unroll
                for (int k = 0; k < 9; k++) {
                    const int dy = k / 3, dx = k % 3;
                    float v0 = v[dy][dx], v1 = v[dy][dx + 1];
                    const float* wb = &s_w[bb][(ci * 9 + k) * 16];
                    #pragma unroll
                    for (int q = 0; q < 4; q++) {
                        float4 wq = *(const float4*)(wb + q * 4);
                        acc[0][q*4+0] += v0 * wq.x;  acc[1][q*4+0] += v1 * wq.x;
                        acc[0][q*4+1] += v0 * wq.y;  acc[1][q*4+1] += v1 * wq.y;
                        acc[0][q*4+2] += v0 * wq.z;  acc[1][q*4+2] += v1 * wq.z;
                        acc[0][q*4+3] += v0 * wq.w;  acc[1][q*4+3] += v1 * wq.w;
                    }
                }
            }
        }
        __syncthreads();
    }

    if (!active) return;
    const int pix0 = y * 21 + x0;
    #pragma unroll
    for (int j = 0; j < 16; j++) {
        int co = coB + j;
        float bv = bias[co];
        float* op = &out[((size_t)n * 256 + co) * NP2 + pix0];
        op[0] = fmaxf(acc[0][j] + bv, 0.0f);
        if (has2) op[1] = fmaxf(acc[1][j] + bv, 0.0f);
    }
}

// ---------------------------------------------------------------------------
// decoder: FOLDED upsample(2x nearest)+conv3x3+bias+relu.
// 256 threads; thread = 2 adjacent original pixels -> 2x(2x2) outputs, 8 couts.
// Per ci: 12 input LDS + 32 broadcast LDS.128 -> 256 FFMA. Double-buffered.
// ---------------------------------------------------------------------------
template<int CIN>
__global__ void __launch_bounds__(256) k_dec_up(
    const float* __restrict__ in, const float* __restrict__ w,
    const float* __restrict__ bias, float* __restrict__ out,
    int Cout, int Hin, int nTilesX)
{
    const int CC = 8;
    __shared__ float s_in[2][CC * 529 + 8];
    __shared__ __align__(16) float s_fw[2][CC * 128];

    const int n   = blockIdx.z;
    const int coB = blockIdx.y * 8;
    const int tY  = blockIdx.x / nTilesX;
    const int tX  = blockIdx.x % nTilesX;
    const int y0  = tY * 21, x0t = tX * 21;
    const int tid = threadIdx.x;
    const int y   = tid / 11;
    const int xp  = tid % 11;
    const int x0  = 2 * xp;
    const bool active = (tid < 231);
    const bool has2   = active && (xp < 10);

    float acc[2][8][4];
    #pragma unroll
    for (int p = 0; p < 2; p++)
        #pragma unroll
        for (int j = 0; j < 8; j++)
            { acc[p][j][0]=acc[p][j][1]=acc[p][j][2]=acc[p][j][3]=0.f; }

    const float* inN = in + (size_t)n * CIN * Hin * Hin;

    auto fill = [&](int bb, int cc) {
        #pragma unroll 1
        for (int idx = tid; idx < CC * 529; idx += 256) {
            int ci = idx / 529, rem = idx % 529;
            int r = rem / 23, c = rem % 23;
            int gy = y0 - 1 + r, gx = x0t - 1 + c;
            float v = 0.0f;
            if (gy >= 0 && gy < Hin && gx >= 0 && gx < Hin)
                v = inN[((size_t)(cc + ci) * Hin + gy) * Hin + gx];
            s_in[bb][idx] = v;
        }
        #pragma unroll 1
        for (int idx = tid; idx < CC * 128; idx += 256) {
            int ci = idx >> 7;
            int pt = (idx >> 3) & 15;
            int co = idx & 7;
            int par = pt >> 2, tap = pt & 3;
            int py = par >> 1, px = par & 1, a = tap >> 1, b = tap & 1;
            const float* wb = &w[((size_t)(coB + co) * CIN + cc + ci) * 9];
            int rlo, rhi, clo, chi;
            if (py == 0) { if (a == 0) { rlo = 0; rhi = 0; } else { rlo = 1; rhi = 2; } }
            else         { if (a == 0) { rlo = 0; rhi = 1; } else { rlo = 2; rhi = 2; } }
            if (px == 0) { if (b == 0) { clo = 0; chi = 0; } else { clo = 1; chi = 2; } }
            else         { if (b == 0) { clo = 0; chi = 1; } else { clo = 2; chi = 2; } }
            float s = 0.0f;
            for (int r = rlo; r <= rhi; r++)
                for (int c = clo; c <= chi; c++)
                    s += wb[r * 3 + c];
            s_fw[bb][idx] = s;
        }
    };

    fill(0, 0);
    __syncthreads();

    const int NIT = CIN / CC;
    for (int it = 0; it < NIT; it++) {
        int bb = it & 1;
        if (it + 1 < NIT) fill(bb ^ 1, (it + 1) * CC);
        if (active) {
            #pragma unroll
            for (int ci = 0; ci < CC; ci++) {
                const float* si = &s_in[bb][ci * 529 + y * 23 + x0];
                float v[3][4];
                #pragma unroll
                for (int r = 0; r < 3; r++) {
                    v[r][0] = si[r*23+0]; v[r][1] = si[r*23+1];
                    v[r][2] = si[r*23+2]; v[r][3] = si[r*23+3];
                }
                const float* fw = &s_fw[bb][ci * 128];
                #pragma unroll
                for (int par = 0; par < 4; par++) {
                    const int py = par >> 1, px = par & 1;
                    #pragma unroll
                    for (int tap = 0; tap < 4; tap++) {
                        const int a = tap >> 1, b = tap & 1;
                        float v0 = v[py + a][px + b];
                        float v1 = v[py + a][px + b + 1];
                        float4 wA = *(const float4*)&fw[(par * 4 + tap) * 8];
                        float4 wB = *(const float4*)&fw[(par * 4 + tap) * 8 + 4];
                        acc[0][0][par] += v0 * wA.x;  acc[1][0][par] += v1 * wA.x;
                        acc[0][1][par] += v0 * wA.y;  acc[1][1][par] += v1 * wA.y;
                        acc[0][2][par] += v0 * wA.z;  acc[1][2][par] += v1 * wA.z;
                        acc[0][3][par] += v0 * wA.w;  acc[1][3][par] += v1 * wA.w;
                        acc[0][4][par] += v0 * wB.x;  acc[1][4][par] += v1 * wB.x;
                        acc[0][5][par] += v0 * wB.y;  acc[1][5][par] += v1 * wB.y;
                        acc[0][6][par] += v0 * wB.z;  acc[1][6][par] += v1 * wB.z;
                        acc[0][7][par] += v0 * wB.w;  acc[1][7][par] += v1 * wB.w;
                    }
                }
            }
        }
        __syncthreads();
    }

    if (!active) return;
    const int Hout = Hin * 2;
    const int oy = y0 + y;
    #pragma unroll
    for (int j = 0; j < 8; j++) {
        int co = coB + j;
        float bv = bias[co];
        #pragma unroll
        for (int pxi = 0; pxi < 2; pxi++) {
            if (pxi == 1 && !has2) break;
            int ox = x0t + x0 + pxi;
            #pragma unroll
            for (int py = 0; py < 2; py++) {
                float2 o;
                o.x = fmaxf(acc[pxi][j][py * 2 + 0] + bv, 0.0f);
                o.y = fmaxf(acc[pxi][j][py * 2 + 1] + bv, 0.0f);
                size_t off = (((size_t)n * Cout + co) * Hout + oy * 2 + py) * Hout
                             + (size_t)ox * 2;
                *(float2*)&out[off] = o;
            }
        }
    }
}

// ---------------------------------------------------------------------------
// depthwise conv 3x3, groups=512, no bias. input = concat(feat[t], h)
// ---------------------------------------------------------------------------
__global__ void __launch_bounds__(448) k_dw(
    const float* __restrict__ dww, int t)
{
    __shared__ float s[NP2];
    const int ch = blockIdx.x;
    const int b  = blockIdx.y;
    const int tid = threadIdx.x;

    const float* src = (ch < 256)
        ? &g_feat[((size_t)(b * TT + t) * 256 + ch) * NP2]
        : &g_h[((size_t)b * HD + (ch - 256)) * NP2];

    if (tid < NP2) s[tid] = src[tid];
    __syncthreads();
    if (tid >= NP2) return;

    float wr[9];
    #pragma unroll
    for (int k = 0; k < 9; k++) wr[k] = __ldg(&dww[(size_t)ch * 9 + k]);

    int y = tid / 21, x = tid % 21;
    float acc = 0.0f;
    #pragma unroll
    for (int k = 0; k < 9; k++) {
        int iy = y + k / 3 - 1, ix = x + k % 3 - 1;
        if (iy >= 0 && iy < 21 && ix >= 0 && ix < 21)
            acc += s[iy * 21 + ix] * wr[k];
    }
    g_gdw[((size_t)b * 512 + ch) * NP2 + tid] = acc;
}

// ---------------------------------------------------------------------------
// pointwise 1x1 512->1024 + bias, fused LSTM gates.
// 256 threads; thread = 2 pixels x 8 couts (x4 gates). Double-buffered.
// Per ci: 2 input LDS + 8 broadcast LDS.128 -> 64 FFMA.
// ---------------------------------------------------------------------------
__global__ void __launch_bounds__(256) k_pw_gates(
    const float* __restrict__ pww, const float* __restrict__ pwb, int t)
{
    const int CC = 8;
    __shared__ float s_in[2][CC * NP2 + 8];
    __shared__ __align__(16) float s_w[2][CC * 32];

    const int coB = blockIdx.x * 8;
    const int b   = blockIdx.y;
    const int tid = threadIdx.x;
    const int p0  = 2 * tid;
    const bool a0 = (p0 < NP2);
    const bool a1 = (p0 + 1 < NP2);

    float acc[2][32];   // [pixel][gate*8+co]
    #pragma unroll
    for (int p = 0; p < 2; p++)
        #pragma unroll
        for (int j = 0; j < 32; j++) acc[p][j] = 0.0f;

    auto fill = [&](int bb, int cc) {
        #pragma unroll 1
        for (int idx = tid; idx < CC * NP2; idx += 256) {
            int ci = idx / NP2, p = idx % NP2;
            s_in[bb][idx] = g_gdw[((size_t)b * 512 + cc + ci) * NP2 + p];
        }
        if (tid < CC * 32) {
            int ci = tid >> 5, j = tid & 31;
            int gate = j >> 3, co = j & 7;
            s_w[bb][tid] = pww[((size_t)(gate * 256 + coB + co)) * 512 + cc + ci];
        }
    };

    fill(0, 0);
    __syncthreads();

    for (int it = 0; it < 64; it++) {
        int bb = it & 1;
        if (it + 1 < 64) fill(bb ^ 1, (it + 1) * CC);
        if (a0) {
            #pragma unroll
            for (int ci = 0; ci < CC; ci++) {
                float v0 = s_in[bb][ci * NP2 + p0];
                float v1 = s_in[bb][ci * NP2 + p0 + 1];   // junk if !a1, never stored
                const float* fw = &s_w[bb][ci * 32];
                #pragma unroll
                for (int q = 0; q < 8; q++) {
                    float4 wq = *(const float4*)(fw + q * 4);
                    acc[0][q*4+0] += v0 * wq.x;  acc[1][q*4+0] += v1 * wq.x;
                    acc[0][q*4+1] += v0 * wq.y;  acc[1][q*4+1] += v1 * wq.y;
                    acc[0][q*4+2] += v0 * wq.z;  acc[1][q*4+2] += v1 * wq.z;
                    acc[0][q*4+3] += v0 * wq.w;  acc[1][q*4+3] += v1 * wq.w;
                }
            }
        }
        __syncthreads();
    }

    if (!a0) return;
    #pragma unroll
    for (int co = 0; co < 8; co++) {
        int cg = coB + co;
        float bi = pwb[cg], bf = pwb[256 + cg], bo = pwb[512 + cg], bg = pwb[768 + cg];
        #pragma unroll
        for (int p = 0; p < 2; p++) {
            if (p == 1 && !a1) break;
            float iv = sigm(acc[p][co]      + bi);
            float fv = sigm(acc[p][8 + co]  + bf);
            float ov = sigm(acc[p][16 + co] + bo);
            float gv = tanhf(acc[p][24 + co] + bg);
            size_t off = ((size_t)b * HD + cg) * NP2 + p0 + p;
            float c2 = fv * g_c[off] + iv * gv;
            float h2 = ov * tanhf(c2);
            g_c[off] = c2;
            g_h[off] = h2;
            g_hs[((size_t)(b * TT + t) * 256 + cg) * NP2 + p0 + p] = h2;
        }
    }
}

// ---------------------------------------------------------------------------
// dec3: 1x1 conv 64->1 + bias.
// ---------------------------------------------------------------------------
__global__ void k_dec3(const float* __restrict__ w, const float* __restrict__ bias,
                       float* __restrict__ out)
{
    __shared__ float s_w[64];
    if (threadIdx.x < 64) s_w[threadIdx.x] = w[threadIdx.x];
    __syncthreads();

    int idx = blockIdx.x * blockDim.x + threadIdx.x;
    if (idx >= OUTN) return;
    int n = idx / NP0, pix = idx % NP0;
    const float* d = &g_d2[(size_t)n * 64 * NP0 + pix];
    float acc = bias[0];
    #pragma unroll
    for (int c = 0; c < 64; c++) acc += d[(size_t)c * NP0] * s_w[c];
    out[idx] = acc;
}

__global__ void k_copy_hc(float* __restrict__ out)
{
    int i = blockIdx.x * blockDim.x + threadIdx.x;
    if (i < BB * HD * NP2) {
        out[OUTN + i]     = g_h[i];
        out[2 * OUTN + i] = g_c[i];
    }
}

// ---------------------------------------------------------------------------
extern "C" void kernel_launch(void* const* d_in, const int* in_sizes, int n_in,
                              void* d_out, int out_size)
{
    const float* x      = (const float*)d_in[0];
    const float* enc_w1 = (const float*)d_in[1];
    const float* enc_b1 = (const float*)d_in[2];
    const float* enc_w2 = (const float*)d_in[3];
    const float* enc_b2 = (const float*)d_in[4];
    const float* enc_w3 = (const float*)d_in[5];
    const float* enc_b3 = (const float*)d_in[6];
    const float* dw_w   = (const float*)d_in[7];
    const float* pw_w   = (const float*)d_in[8];
    const float* pw_b   = (const float*)d_in[9];
    const float* dec_w1 = (const float*)d_in[10];
    const float* dec_b1 = (const float*)d_in[11];
    const float* dec_w2 = (const float*)d_in[12];
    const float* dec_b2 = (const float*)d_in[13];
    const float* dec_w3 = (const float*)d_in[14];
    const float* dec_b3 = (const float*)d_in[15];
    float* out = (float*)d_out;

    float *e1, *e2, *feat, *hs, *d1, *d2;
    cudaGetSymbolAddress((void**)&e1,   g_e1);
    cudaGetSymbolAddress((void**)&e2,   g_e2);
    cudaGetSymbolAddress((void**)&feat, g_feat);
    cudaGetSymbolAddress((void**)&hs,   g_hs);
    cudaGetSymbolAddress((void**)&d1,   g_d1);
    cudaGetSymbolAddress((void**)&d2,   g_d2);

    k_zero_hc<<<(BB * HD * NP2 + 255) / 256, 256>>>();

    // encoder
    k_enc1<<<dim3(4, 1, BT), 448>>>(x, enc_w1, enc_b1, e1);
    k_conv_pool<<<dim3(1, 128 / 8, BT), 448>>>(e1, enc_w2, enc_b2, e2, 64, 128, 42);
    k_enc3<<<dim3(256 / 16, BT), 256>>>(e2, enc_w3, enc_b3, feat);

    // ConvLSTM over T=16 steps
    for (int t = 0; t < TT; t++) {
        k_dw<<<dim3(512, BB), 448>>>(dw_w, t);
        k_pw_gates<<<dim3(32, BB), 256>>>(pw_w, pw_b, t);
    }

    // decoder with folded nearest-upsample conv
    k_dec_up<256><<<dim3(1, 128 / 8, BT), 256>>>(hs, dec_w1, dec_b1, d1, 128, 21, 1);
    k_dec_up<128><<<dim3(4, 64 / 8, BT), 256>>>(d1, dec_w2, dec_b2, d2, 64, 42, 2);
    k_dec3<<<(OUTN + 255) / 256, 256>>>(dec_w3, dec_b3, out);

    if (out_size >= 3 * OUTN)
        k_copy_hc<<<(BB * HD * NP2 + 255) / 256, 256>>>(out);
}

// round 4
// speedup vs baseline: 1.0972x; 1.0972x over previous
#include <cuda_runtime.h>
#include <cuda_bf16.h>
#include <math.h>

// ---------------------------------------------------------------------------
//   x: (8,16,3,84,84)  B=8 T=16  -> BT=128 frames
//   enc: 3->64 (pool), 64->128 (pool), 128->256    @84/42/21
//   ConvLSTM: depthwise 3x3 g=512, pointwise 512->1024, gates
//   dec: up2 conv 256->128 @42, up2 conv 128->64 @84, 1x1 64->1
// ---------------------------------------------------------------------------

#define BT   128
#define BB   8
#define TT   16
#define HD   256
#define NP2  441
#define NP1  1764
#define NP0  7056
#define OUTN 903168

typedef unsigned long long u64;

__device__ float g_e1  [BT * 64  * NP1];
__device__ float g_e2  [BT * 128 * NP2];
__device__ float g_feat[BT * 256 * NP2];
__device__ float g_gdwf[BT * 256 * NP2];   // depthwise(feat) for ALL frames
__device__ float g_gdwh[BB * 256 * NP2];   // depthwise(h) for current step
__device__ float g_hs  [BT * 256 * NP2];
__device__ float g_d1  [BT * 128 * NP1];
__device__ float g_d2  [BT * 64  * NP0];
__device__ float g_h   [BB * HD * NP2];
__device__ float g_c   [BB * HD * NP2];

__device__ __forceinline__ float sigm(float x) { return 1.0f / (1.0f + expf(-x)); }

// packed fp32x2 helpers (FFMA2 — 2 MACs per issue slot on sm_103a)
__device__ __forceinline__ u64 pack2(float a, float b) {
    u64 r; asm("mov.b64 %0, {%1, %2};" : "=l"(r) : "f"(a), "f"(b)); return r;
}
__device__ __forceinline__ void fma2(u64& acc, u64 a, u64 b) {
    asm("fma.rn.f32x2 %0, %1, %2, %0;" : "+l"(acc) : "l"(a), "l"(b));
}
__device__ __forceinline__ float2 unpack2(u64 v) {
    float2 r; asm("mov.b64 {%0, %1}, %2;" : "=f"(r.x), "=f"(r.y) : "l"(v)); return r;
}

__global__ void k_zero_hc()
{
    int i = blockIdx.x * blockDim.x + threadIdx.x;
    if (i < BB * HD * NP2) { g_h[i] = 0.0f; g_c[i] = 0.0f; }
}

// ---------------------------------------------------------------------------
// enc1: conv3x3 3->64 + bias + relu + maxpool2.  84x84 -> pooled 42x42
// (small layer; unchanged)
// ---------------------------------------------------------------------------
__global__ void __launch_bounds__(448) k_enc1(
    const float* __restrict__ x, const float* __restrict__ w,
    const float* __restrict__ bias, float* __restrict__ out)
{
    __shared__ float s_in[3 * 44 * 44];
    __shared__ __align__(16) float s_w[3 * 9 * 64];

    const int n   = blockIdx.z;
    const int bx  = blockIdx.x;
    const int py0 = (bx >> 1) * 21;
    const int px0 = (bx & 1) * 21;
    const int oy0 = py0 * 2;
    const int ox0 = px0 * 2;
    const int tid = threadIdx.x;

    const float* xn = x + (size_t)n * 3 * NP0;

    for (int idx = tid; idx < 3 * 44 * 44; idx += 448) {
        int ci = idx / 1936, rem = idx % 1936;
        int r = rem / 44, c = rem % 44;
        int gy = oy0 - 1 + r, gx = ox0 - 1 + c;
        float v = 0.0f;
        if (gy >= 0 && gy < 84 && gx >= 0 && gx < 84)
            v = xn[(size_t)ci * NP0 + gy * 84 + gx];
        s_in[idx] = v;
    }
    for (int idx = tid; idx < 3 * 9 * 64; idx += 448) {
        int ci = idx / (9 * 64); int k = (idx % (9 * 64)) / 64; int co = idx % 64;
        s_w[idx] = w[((size_t)co * 3 + ci) * 9 + k];
    }
    __syncthreads();
    if (tid >= 441) return;

    const int ty = tid / 21, tx = tid % 21;
    const int by = 2 * ty, bxp = 2 * tx;

    for (int cg = 0; cg < 8; cg++) {
        float acc[8][4];
        #pragma unroll
        for (int j = 0; j < 8; j++) { acc[j][0]=acc[j][1]=acc[j][2]=acc[j][3]=0.f; }
        #pragma unroll
        for (int ci = 0; ci < 3; ci++) {
            const float* si = &s_in[ci * 1936];
            #pragma unroll
            for (int k = 0; k < 9; k++) {
                int dy = k / 3, dx = k % 3;
                const float* p0 = si + (by + dy) * 44 + (bxp + dx);
                float v00 = p0[0], v01 = p0[1], v10 = p0[44], v11 = p0[45];
                float4 wA = *(const float4*)&s_w[(ci * 9 + k) * 64 + cg * 8];
                float4 wB = *(const float4*)&s_w[(ci * 9 + k) * 64 + cg * 8 + 4];
                float wv[8] = {wA.x, wA.y, wA.z, wA.w, wB.x, wB.y, wB.z, wB.w};
                #pragma unroll
                for (int j = 0; j < 8; j++) {
                    acc[j][0] += v00 * wv[j];
                    acc[j][1] += v01 * wv[j];
                    acc[j][2] += v10 * wv[j];
                    acc[j][3] += v11 * wv[j];
                }
            }
        }
        #pragma unroll
        for (int j = 0; j < 8; j++) {
            int co = cg * 8 + j;
            float m = fmaxf(fmaxf(acc[j][0], acc[j][1]), fmaxf(acc[j][2], acc[j][3]));
            m = fmaxf(m + bias[co], 0.0f);
            out[(((size_t)n * 64 + co) * 42 + py0 + ty) * 42 + px0 + tx] = m;
        }
    }
}

// ---------------------------------------------------------------------------
// enc2: conv3x3 64->128 + bias + relu + maxpool2 @42 -> 21.  FFMA2 inner loop.
// acc: [4 cout-pairs][4 positions] as f32x2.
// ---------------------------------------------------------------------------
__global__ void __launch_bounds__(448) k_conv_pool(
    const float* __restrict__ in, const float* __restrict__ w,
    const float* __restrict__ bias, float* __restrict__ out,
    int Cin, int Cout, int Hc)
{
    const int CC = 4;
    __shared__ float s_in[CC * 44 * 44];
    __shared__ __align__(16) float s_w[CC * 9 * 8];

    const int n   = blockIdx.z;
    const int coB = blockIdx.y * 8;
    const int tid = threadIdx.x;
    const int ty = tid / 21, tx = tid % 21;
    const int by = 2 * ty, bxp = 2 * tx;

    u64 acc[4][4];
    #pragma unroll
    for (int q = 0; q < 4; q++)
        #pragma unroll
        for (int p = 0; p < 4; p++) acc[q][p] = 0ULL;

    const float* inN = in + (size_t)n * Cin * Hc * Hc;

    for (int cc = 0; cc < Cin; cc += CC) {
        for (int idx = tid; idx < CC * 44 * 44; idx += 448) {
            int ci = idx / 1936, rem = idx % 1936;
            int r = rem / 44, c = rem % 44;
            int gy = r - 1, gx = c - 1;
            float v = 0.0f;
            if (gy >= 0 && gy < Hc && gx >= 0 && gx < Hc)
                v = inN[((size_t)(cc + ci) * Hc + gy) * Hc + gx];
            s_in[idx] = v;
        }
        for (int idx = tid; idx < CC * 9 * 8; idx += 448) {
            int ci = idx / 72; int k = (idx % 72) / 8; int co = idx % 8;
            s_w[idx] = w[((size_t)(coB + co) * Cin + (cc + ci)) * 9 + k];
        }
        __syncthreads();
        if (tid < 441) {
            #pragma unroll
            for (int ci = 0; ci < CC; ci++) {
                const float* si = &s_in[ci * 1936];
                #pragma unroll
                for (int k = 0; k < 9; k++) {
                    int dy = k / 3, dx = k % 3;
                    const float* p0 = si + (by + dy) * 44 + (bxp + dx);
                    u64 vp0 = pack2(p0[0],  p0[0]);
                    u64 vp1 = pack2(p0[1],  p0[1]);
                    u64 vp2 = pack2(p0[44], p0[44]);
                    u64 vp3 = pack2(p0[45], p0[45]);
                    const ulonglong2* wb = (const ulonglong2*)&s_w[(ci * 9 + k) * 8];
                    ulonglong2 w0 = wb[0], w1 = wb[1];
                    fma2(acc[0][0], vp0, w0.x); fma2(acc[0][1], vp1, w0.x);
                    fma2(acc[0][2], vp2, w0.x); fma2(acc[0][3], vp3, w0.x);
                    fma2(acc[1][0], vp0, w0.y); fma2(acc[1][1], vp1, w0.y);
                    fma2(acc[1][2], vp2, w0.y); fma2(acc[1][3], vp3, w0.y);
                    fma2(acc[2][0], vp0, w1.x); fma2(acc[2][1], vp1, w1.x);
                    fma2(acc[2][2], vp2, w1.x); fma2(acc[2][3], vp3, w1.x);
                    fma2(acc[3][0], vp0, w1.y); fma2(acc[3][1], vp1, w1.y);
                    fma2(acc[3][2], vp2, w1.y); fma2(acc[3][3], vp3, w1.y);
                }
            }
        }
        __syncthreads();
    }

    if (tid >= 441) return;
    int Hp = Hc >> 1;
    #pragma unroll
    for (int q = 0; q < 4; q++) {
        float2 a0 = unpack2(acc[q][0]), a1 = unpack2(acc[q][1]);
        float2 a2 = unpack2(acc[q][2]), a3 = unpack2(acc[q][3]);
        int co0 = coB + 2 * q, co1 = co0 + 1;
        float mx = fmaxf(fmaxf(a0.x, a1.x), fmaxf(a2.x, a3.x));
        float my = fmaxf(fmaxf(a0.y, a1.y), fmaxf(a2.y, a3.y));
        mx = fmaxf(mx + bias[co0], 0.0f);
        my = fmaxf(my + bias[co1], 0.0f);
        out[(((size_t)n * Cout + co0) * Hp + ty) * Hp + tx] = mx;
        out[(((size_t)n * Cout + co1) * Hp + ty) * Hp + tx] = my;
    }
}

// ---------------------------------------------------------------------------
// enc3: conv3x3 128->256 + bias + relu @21x21.  FFMA2, 32 couts as 16 pairs.
// ---------------------------------------------------------------------------
__global__ void __launch_bounds__(448) k_enc3(
    const float* __restrict__ in, const float* __restrict__ w,
    const float* __restrict__ bias, float* __restrict__ out)
{
    const int CC = 8;
    __shared__ float s_in[CC * 529];
    __shared__ __align__(16) float s_w[CC * 9 * 32];

    const int coB = blockIdx.x * 32;
    const int n   = blockIdx.y;
    const int tid = threadIdx.x;
    const int y = tid / 21, x = tid % 21;

    u64 acc[16];
    #pragma unroll
    for (int j = 0; j < 16; j++) acc[j] = 0ULL;

    const float* inN = in + (size_t)n * 128 * NP2;

    for (int cc = 0; cc < 128; cc += CC) {
        for (int idx = tid; idx < CC * 529; idx += 448) {
            int ci = idx / 529, rem = idx % 529;
            int r = rem / 23, c = rem % 23;
            int gy = r - 1, gx = c - 1;
            float v = 0.0f;
            if (gy >= 0 && gy < 21 && gx >= 0 && gx < 21)
                v = inN[(size_t)(cc + ci) * NP2 + gy * 21 + gx];
            s_in[idx] = v;
        }
        for (int idx = tid; idx < CC * 9 * 32; idx += 448) {
            int ci = idx / 288; int k = (idx % 288) / 32; int co = idx % 32;
            s_w[idx] = w[((size_t)(coB + co) * 128 + (cc + ci)) * 9 + k];
        }
        __syncthreads();
        if (tid < 441) {
            #pragma unroll
            for (int ci = 0; ci < CC; ci++) {
                const float* si = &s_in[ci * 529 + y * 23 + x];
                float v[9];
                #pragma unroll
                for (int r = 0; r < 3; r++) {
                    v[r*3+0] = si[r*23+0]; v[r*3+1] = si[r*23+1]; v[r*3+2] = si[r*23+2];
                }
                #pragma unroll
                for (int k = 0; k < 9; k++) {
                    u64 vv = pack2(v[k], v[k]);
                    const ulonglong2* wb = (const ulonglong2*)&s_w[(ci * 9 + k) * 32];
                    #pragma unroll
                    for (int q = 0; q < 8; q++) {
                        ulonglong2 wp = wb[q];
                        fma2(acc[2*q],   vv, wp.x);
                        fma2(acc[2*q+1], vv, wp.y);
                    }
                }
            }
        }
        __syncthreads();
    }

    if (tid >= 441) return;
    #pragma unroll
    for (int p = 0; p < 16; p++) {
        float2 a = unpack2(acc[p]);
        int co0 = coB + 2 * p, co1 = co0 + 1;
        out[((size_t)n * 256 + co0) * NP2 + tid] = fmaxf(a.x + bias[co0], 0.0f);
        out[((size_t)n * 256 + co1) * NP2 + tid] = fmaxf(a.y + bias[co1], 0.0f);
    }
}

// ---------------------------------------------------------------------------
// decoder: FOLDED upsample(2x nearest)+conv3x3+bias+relu.  FFMA2.
// acc: [4 cout-pairs][4 parities].
// ---------------------------------------------------------------------------
template<int CIN>
__global__ void __launch_bounds__(448) k_dec_up(
    const float* __restrict__ in, const float* __restrict__ w,
    const float* __restrict__ bias, float* __restrict__ out,
    int Cout, int Hin, int nTilesX)
{
    const int CC = 8;
    __shared__ float s_in[CC * 529];
    __shared__ __align__(16) float s_fw[CC * 16 * 8];

    const int n   = blockIdx.z;
    const int coB = blockIdx.y * 8;
    const int tY  = blockIdx.x / nTilesX;
    const int tX  = blockIdx.x % nTilesX;
    const int y0  = tY * 21, x0t = tX * 21;
    const int tid = threadIdx.x;
    const int ty = tid / 21, tx = tid % 21;

    u64 acc[4][4];
    #pragma unroll
    for (int q = 0; q < 4; q++)
        #pragma unroll
        for (int p = 0; p < 4; p++) acc[q][p] = 0ULL;

    const float* inN = in + (size_t)n * CIN * Hin * Hin;

    for (int cc = 0; cc < CIN; cc += CC) {
        for (int idx = tid; idx < CC * 529; idx += 448) {
            int ci = idx / 529, rem = idx % 529;
            int r = rem / 23, c = rem % 23;
            int gy = y0 - 1 + r, gx = x0t - 1 + c;
            float v = 0.0f;
            if (gy >= 0 && gy < Hin && gx >= 0 && gx < Hin)
                v = inN[((size_t)(cc + ci) * Hin + gy) * Hin + gx];
            s_in[idx] = v;
        }
        // fold 3x3 weights into per-parity 2x2 taps
        for (int idx = tid; idx < CC * 128; idx += 448) {
            int ci = idx >> 7;
            int pt = (idx >> 3) & 15;
            int co = idx & 7;
            int par = pt >> 2, tap = pt & 3;
            int py = par >> 1, px = par & 1, a = tap >> 1, b = tap & 1;
            const float* wb = &w[((size_t)(coB + co) * CIN + cc + ci) * 9];
            int rlo, rhi, clo, chi;
            if (py == 0) { if (a == 0) { rlo = 0; rhi = 0; } else { rlo = 1; rhi = 2; } }
            else         { if (a == 0) { rlo = 0; rhi = 1; } else { rlo = 2; rhi = 2; } }
            if (px == 0) { if (b == 0) { clo = 0; chi = 0; } else { clo = 1; chi = 2; } }
            else         { if (b == 0) { clo = 0; chi = 1; } else { clo = 2; chi = 2; } }
            float s = 0.0f;
            for (int r = rlo; r <= rhi; r++)
                for (int c = clo; c <= chi; c++)
                    s += wb[r * 3 + c];
            s_fw[idx] = s;
        }
        __syncthreads();
        if (tid < 441) {
            #pragma unroll
            for (int ci = 0; ci < CC; ci++) {
                const float* si = &s_in[ci * 529 + ty * 23 + tx];
                float v[3][3];
                #pragma unroll
                for (int r = 0; r < 3; r++) {
                    v[r][0] = si[r*23+0]; v[r][1] = si[r*23+1]; v[r][2] = si[r*23+2];
                }
                const float* fw = &s_fw[ci * 128];
                #pragma unroll
                for (int par = 0; par < 4; par++) {
                    const int py = par >> 1, px = par & 1;
                    #pragma unroll
                    for (int tap = 0; tap < 4; tap++) {
                        const int a = tap >> 1, b = tap & 1;
                        u64 vv = pack2(v[py + a][px + b], v[py + a][px + b]);
                        const ulonglong2* wb = (const ulonglong2*)&fw[(par * 4 + tap) * 8];
                        ulonglong2 w0 = wb[0], w1 = wb[1];
                        fma2(acc[0][par], vv, w0.x);
                        fma2(acc[1][par], vv, w0.y);
                        fma2(acc[2][par], vv, w1.x);
                        fma2(acc[3][par], vv, w1.y);
                    }
                }
            }
        }
        __syncthreads();
    }

    if (tid >= 441) return;
    const int Hout = Hin * 2;
    #pragma unroll
    for (int q = 0; q < 4; q++) {
        float2 a[4];
        #pragma unroll
        for (int par = 0; par < 4; par++) a[par] = unpack2(acc[q][par]);
        #pragma unroll
        for (int lane = 0; lane < 2; lane++) {
            int co = coB + 2 * q + lane;
            float bv = bias[co];
            #pragma unroll
            for (int py = 0; py < 2; py++) {
                float u0 = lane ? a[py*2+0].y : a[py*2+0].x;
                float u1 = lane ? a[py*2+1].y : a[py*2+1].x;
                float2 o;
                o.x = fmaxf(u0 + bv, 0.0f);
                o.y = fmaxf(u1 + bv, 0.0f);
                size_t off = (((size_t)n * Cout + co) * Hout + (y0 + ty) * 2 + py) * Hout
                             + (size_t)(x0t + tx) * 2;
                *(float2*)&out[off] = o;
            }
        }
    }
}

// ---------------------------------------------------------------------------
// depthwise conv 3x3 — feat half (channels 0..255), ALL frames, one launch
// ---------------------------------------------------------------------------
__global__ void __launch_bounds__(448) k_dw_feat(const float* __restrict__ dww)
{
    __shared__ float s[NP2];
    const int ch  = blockIdx.x;   // 0..255
    const int n   = blockIdx.y;   // frame 0..127
    const int tid = threadIdx.x;

    const float* src = &g_feat[((size_t)n * 256 + ch) * NP2];
    if (tid < NP2) s[tid] = src[tid];
    __syncthreads();
    if (tid >= NP2) return;

    float wr[9];
    #pragma unroll
    for (int k = 0; k < 9; k++) wr[k] = __ldg(&dww[(size_t)ch * 9 + k]);

    int y = tid / 21, x = tid % 21;
    float acc = 0.0f;
    #pragma unroll
    for (int k = 0; k < 9; k++) {
        int iy = y + k / 3 - 1, ix = x + k % 3 - 1;
        if (iy >= 0 && iy < 21 && ix >= 0 && ix < 21)
            acc += s[iy * 21 + ix] * wr[k];
    }
    g_gdwf[((size_t)n * 256 + ch) * NP2 + tid] = acc;
}

// depthwise conv — h half (channels 256..511), per step
__global__ void __launch_bounds__(448) k_dw_h(const float* __restrict__ dww)
{
    __shared__ float s[NP2];
    const int ch  = blockIdx.x;   // 0..255 (h channel)
    const int b   = blockIdx.y;
    const int tid = threadIdx.x;

    const float* src = &g_h[((size_t)b * HD + ch) * NP2];
    if (tid < NP2) s[tid] = src[tid];
    __syncthreads();
    if (tid >= NP2) return;

    float wr[9];
    #pragma unroll
    for (int k = 0; k < 9; k++) wr[k] = __ldg(&dww[(size_t)(256 + ch) * 9 + k]);

    int y = tid / 21, x = tid % 21;
    float acc = 0.0f;
    #pragma unroll
    for (int k = 0; k < 9; k++) {
        int iy = y + k / 3 - 1, ix = x + k % 3 - 1;
        if (iy >= 0 && iy < 21 && ix >= 0 && ix < 21)
            acc += s[iy * 21 + ix] * wr[k];
    }
    g_gdwh[((size_t)b * 256 + ch) * NP2 + tid] = acc;
}

// ---------------------------------------------------------------------------
// pointwise 1x1 512->1024 + bias, fused LSTM gates.  FFMA2.
// grid (32 cout-groups, 8 batch, 2 pixel-halves); 256 threads, 1 px/thread.
// acc layout: [gate*4 + cout-pair] as f32x2.
// ---------------------------------------------------------------------------
__global__ void __launch_bounds__(256) k_pw_gates(
    const float* __restrict__ pww, const float* __restrict__ pwb, int t)
{
    const int CC = 16;
    __shared__ float s_in[CC * 224];
    __shared__ __align__(16) float s_w[CC * 32];

    const int coB  = blockIdx.x * 8;
    const int b    = blockIdx.y;
    const int half = blockIdx.z;
    const int tid  = threadIdx.x;
    const int gp   = half * 224 + tid;
    const bool act = (tid < 224) && (gp < NP2);

    u64 acc[16];
    #pragma unroll
    for (int j = 0; j < 16; j++) acc[j] = 0ULL;

    for (int cc = 0; cc < 512; cc += CC) {
        for (int idx = tid; idx < CC * 224; idx += 256) {
            int ci = idx / 224, p = idx % 224;
            int pp = half * 224 + p;
            int c  = cc + ci;
            float v = 0.0f;
            if (pp < NP2)
                v = (c < 256)
                    ? g_gdwf[((size_t)(b * TT + t) * 256 + c) * NP2 + pp]
                    : g_gdwh[((size_t)b * 256 + (c - 256)) * NP2 + pp];
            s_in[idx] = v;
        }
        for (int idx = tid; idx < CC * 32; idx += 256) {
            int ci = idx >> 5, j = idx & 31;
            int gate = j >> 3, co = j & 7;
            s_w[idx] = pww[((size_t)(gate * 256 + coB + co)) * 512 + cc + ci];
        }
        __syncthreads();
        if (act) {
            #pragma unroll
            for (int ci = 0; ci < CC; ci++) {
                float v = s_in[ci * 224 + tid];
                u64 vv = pack2(v, v);
                const ulonglong2* fw = (const ulonglong2*)&s_w[ci * 32];
                #pragma unroll
                for (int q = 0; q < 8; q++) {
                    ulonglong2 wp = fw[q];
                    fma2(acc[2*q],   vv, wp.x);
                    fma2(acc[2*q+1], vv, wp.y);
                }
            }
        }
        __syncthreads();
    }

    if (!act) return;
    #pragma unroll
    for (int r = 0; r < 4; r++) {
        float2 vi = unpack2(acc[r]);
        float2 vf = unpack2(acc[4 + r]);
        float2 vo = unpack2(acc[8 + r]);
        float2 vg = unpack2(acc[12 + r]);
        #pragma unroll
        for (int lane = 0; lane < 2; lane++) {
            int cg = coB + 2 * r + lane;
            float ia = lane ? vi.y : vi.x;
            float fa = lane ? vf.y : vf.x;
            float oa = lane ? vo.y : vo.x;
            float ga = lane ? vg.y : vg.x;
            float iv = sigm(ia + pwb[cg]);
            float fv = sigm(fa + pwb[256 + cg]);
            float ov = sigm(oa + pwb[512 + cg]);
            float gv = tanhf(ga + pwb[768 + cg]);
            size_t off = ((size_t)b * HD + cg) * NP2 + gp;
            float c2 = fv * g_c[off] + iv * gv;
            float h2 = ov * tanhf(c2);
            g_c[off] = c2;
            g_h[off] = h2;
            g_hs[((size_t)(b * TT + t) * 256 + cg) * NP2 + gp] = h2;
        }
    }
}

// ---------------------------------------------------------------------------
// dec3: 1x1 conv 64->1 + bias.
// ---------------------------------------------------------------------------
__global__ void k_dec3(const float* __restrict__ w, const float* __restrict__ bias,
                       float* __restrict__ out)
{
    __shared__ float s_w[64];
    if (threadIdx.x < 64) s_w[threadIdx.x] = w[threadIdx.x];
    __syncthreads();

    int idx = blockIdx.x * blockDim.x + threadIdx.x;
    if (idx >= OUTN) return;
    int n = idx / NP0, pix = idx % NP0;
    const float* d = &g_d2[(size_t)n * 64 * NP0 + pix];
    float acc = bias[0];
    #pragma unroll
    for (int c = 0; c < 64; c++) acc += d[(size_t)c * NP0] * s_w[c];
    out[idx] = acc;
}

__global__ void k_copy_hc(float* __restrict__ out)
{
    int i = blockIdx.x * blockDim.x + threadIdx.x;
    if (i < BB * HD * NP2) {
        out[OUTN + i]     = g_h[i];
        out[2 * OUTN + i] = g_c[i];
    }
}

// ---------------------------------------------------------------------------
extern "C" void kernel_launch(void* const* d_in, const int* in_sizes, int n_in,
                              void* d_out, int out_size)
{
    const float* x      = (const float*)d_in[0];
    const float* enc_w1 = (const float*)d_in[1];
    const float* enc_b1 = (const float*)d_in[2];
    const float* enc_w2 = (const float*)d_in[3];
    const float* enc_b2 = (const float*)d_in[4];
    const float* enc_w3 = (const float*)d_in[5];
    const float* enc_b3 = (const float*)d_in[6];
    const float* dw_w   = (const float*)d_in[7];
    const float* pw_w   = (const float*)d_in[8];
    const float* pw_b   = (const float*)d_in[9];
    const float* dec_w1 = (const float*)d_in[10];
    const float* dec_b1 = (const float*)d_in[11];
    const float* dec_w2 = (const float*)d_in[12];
    const float* dec_b2 = (const float*)d_in[13];
    const float* dec_w3 = (const float*)d_in[14];
    const float* dec_b3 = (const float*)d_in[15];
    float* out = (float*)d_out;

    float *e1, *e2, *feat, *hs, *d1, *d2;
    cudaGetSymbolAddress((void**)&e1,   g_e1);
    cudaGetSymbolAddress((void**)&e2,   g_e2);
    cudaGetSymbolAddress((void**)&feat, g_feat);
    cudaGetSymbolAddress((void**)&hs,   g_hs);
    cudaGetSymbolAddress((void**)&d1,   g_d1);
    cudaGetSymbolAddress((void**)&d2,   g_d2);

    k_zero_hc<<<(BB * HD * NP2 + 255) / 256, 256>>>();

    // encoder
    k_enc1<<<dim3(4, 1, BT), 448>>>(x, enc_w1, enc_b1, e1);
    k_conv_pool<<<dim3(1, 128 / 8, BT), 448>>>(e1, enc_w2, enc_b2, e2, 64, 128, 42);
    k_enc3<<<dim3(256 / 32, BT), 448>>>(e2, enc_w3, enc_b3, feat);

    // depthwise(feat) for all 16 steps at once (h-independent)
    k_dw_feat<<<dim3(256, BT), 448>>>(dw_w);

    // ConvLSTM over T=16 steps
    for (int t = 0; t < TT; t++) {
        k_dw_h<<<dim3(256, BB), 448>>>(dw_w);
        k_pw_gates<<<dim3(32, BB, 2), 256>>>(pw_w, pw_b, t);
    }

    // decoder with folded nearest-upsample conv
    k_dec_up<256><<<dim3(1, 128 / 8, BT), 448>>>(hs, dec_w1, dec_b1, d1, 128, 21, 1);
    k_dec_up<128><<<dim3(4, 64 / 8, BT), 448>>>(d1, dec_w2, dec_b2, d2, 64, 42, 2);
    k_dec3<<<(OUTN + 255) / 256, 256>>>(dec_w3, dec_b3, out);

    if (out_size >= 3 * OUTN)
        k_copy_hc<<<(BB * HD * NP2 + 255) / 256, 256>>>(out);
}

// round 5
// speedup vs baseline: 1.2961x; 1.1812x over previous
#include <cuda_runtime.h>
#include <cuda_bf16.h>
#include <math.h>

// ---------------------------------------------------------------------------
//   x: (8,16,3,84,84)  B=8 T=16  -> BT=128 frames
//   enc: 3->64 (pool), 64->128 (pool), 128->256    @84/42/21
//   ConvLSTM: depthwise 3x3 g=512, pointwise 512->1024, gates
//   dec: up2 conv 256->128 @42, up2 conv 128->64 @84, 1x1 64->1
// ---------------------------------------------------------------------------

#define BT   128
#define BB   8
#define TT   16
#define HD   256
#define NP2  441
#define NP1  1764
#define NP0  7056
#define OUTN 903168

__device__ float g_e1  [BT * 64  * NP1];
__device__ float g_e2  [BT * 128 * NP2];
__device__ float g_feat[BT * 256 * NP2];
__device__ float g_gdwf[BT * 256 * NP2];   // depthwise(feat), all frames
__device__ float g_gdwh[BB * 256 * NP2];   // depthwise(h), current step
__device__ float g_pre [BT * 1024 * NP2];  // feat-half of pointwise gates, all frames
__device__ float g_hs  [BT * 256 * NP2];
__device__ float g_d1  [BT * 128 * NP1];
__device__ float g_d2  [BT * 64  * NP0];
__device__ float g_h   [BB * HD * NP2];
__device__ float g_c   [BB * HD * NP2];

__device__ __forceinline__ float sigm(float x) { return 1.0f / (1.0f + expf(-x)); }

__global__ void k_zero_hc()
{
    int i = blockIdx.x * blockDim.x + threadIdx.x;
    if (i < BB * HD * NP2) { g_h[i] = 0.0f; g_c[i] = 0.0f; }
}

// ---------------------------------------------------------------------------
// enc1: conv3x3 3->64 + bias + relu + maxpool2.  84x84 -> pooled 42x42
// ---------------------------------------------------------------------------
__global__ void __launch_bounds__(448) k_enc1(
    const float* __restrict__ x, const float* __restrict__ w,
    const float* __restrict__ bias, float* __restrict__ out)
{
    __shared__ float s_in[3 * 44 * 44];
    __shared__ __align__(16) float s_w[3 * 9 * 64];

    const int n   = blockIdx.z;
    const int bx  = blockIdx.x;
    const int py0 = (bx >> 1) * 21;
    const int px0 = (bx & 1) * 21;
    const int oy0 = py0 * 2;
    const int ox0 = px0 * 2;
    const int tid = threadIdx.x;

    const float* xn = x + (size_t)n * 3 * NP0;

    for (int idx = tid; idx < 3 * 44 * 44; idx += 448) {
        int ci = idx / 1936, rem = idx % 1936;
        int r = rem / 44, c = rem % 44;
        int gy = oy0 - 1 + r, gx = ox0 - 1 + c;
        float v = 0.0f;
        if (gy >= 0 && gy < 84 && gx >= 0 && gx < 84)
            v = xn[(size_t)ci * NP0 + gy * 84 + gx];
        s_in[idx] = v;
    }
    for (int idx = tid; idx < 3 * 9 * 64; idx += 448) {
        int ci = idx / (9 * 64); int k = (idx % (9 * 64)) / 64; int co = idx % 64;
        s_w[idx] = w[((size_t)co * 3 + ci) * 9 + k];
    }
    __syncthreads();
    if (tid >= 441) return;

    const int ty = tid / 21, tx = tid % 21;
    const int by = 2 * ty, bxp = 2 * tx;

    for (int cg = 0; cg < 8; cg++) {
        float acc[8][4];
        #pragma unroll
        for (int j = 0; j < 8; j++) { acc[j][0]=acc[j][1]=acc[j][2]=acc[j][3]=0.f; }
        #pragma unroll
        for (int ci = 0; ci < 3; ci++) {
            const float* si = &s_in[ci * 1936];
            #pragma unroll
            for (int k = 0; k < 9; k++) {
                int dy = k / 3, dx = k % 3;
                const float* p0 = si + (by + dy) * 44 + (bxp + dx);
                float v00 = p0[0], v01 = p0[1], v10 = p0[44], v11 = p0[45];
                float4 wA = *(const float4*)&s_w[(ci * 9 + k) * 64 + cg * 8];
                float4 wB = *(const float4*)&s_w[(ci * 9 + k) * 64 + cg * 8 + 4];
                float wv[8] = {wA.x, wA.y, wA.z, wA.w, wB.x, wB.y, wB.z, wB.w};
                #pragma unroll
                for (int j = 0; j < 8; j++) {
                    acc[j][0] += v00 * wv[j];
                    acc[j][1] += v01 * wv[j];
                    acc[j][2] += v10 * wv[j];
                    acc[j][3] += v11 * wv[j];
                }
            }
        }
        #pragma unroll
        for (int j = 0; j < 8; j++) {
            int co = cg * 8 + j;
            float m = fmaxf(fmaxf(acc[j][0], acc[j][1]), fmaxf(acc[j][2], acc[j][3]));
            m = fmaxf(m + bias[co], 0.0f);
            out[(((size_t)n * 64 + co) * 42 + py0 + ty) * 42 + px0 + tx] = m;
        }
    }
}

// ---------------------------------------------------------------------------
// enc2: conv3x3 64->128 + bias + relu + maxpool2 @42 -> 21 (round-2 version)
// ---------------------------------------------------------------------------
__global__ void __launch_bounds__(448) k_conv_pool(
    const float* __restrict__ in, const float* __restrict__ w,
    const float* __restrict__ bias, float* __restrict__ out,
    int Cin, int Cout, int Hc)
{
    const int CC = 4;
    __shared__ float s_in[CC * 44 * 44];
    __shared__ __align__(16) float s_w[CC * 9 * 8];

    const int n   = blockIdx.z;
    const int coB = blockIdx.y * 8;
    const int tid = threadIdx.x;
    const int ty = tid / 21, tx = tid % 21;
    const int by = 2 * ty, bxp = 2 * tx;

    float acc[8][4];
    #pragma unroll
    for (int j = 0; j < 8; j++) { acc[j][0]=acc[j][1]=acc[j][2]=acc[j][3]=0.f; }

    const float* inN = in + (size_t)n * Cin * Hc * Hc;

    for (int cc = 0; cc < Cin; cc += CC) {
        for (int idx = tid; idx < CC * 44 * 44; idx += 448) {
            int ci = idx / 1936, rem = idx % 1936;
            int r = rem / 44, c = rem % 44;
            int gy = r - 1, gx = c - 1;
            float v = 0.0f;
            if (gy >= 0 && gy < Hc && gx >= 0 && gx < Hc)
                v = inN[((size_t)(cc + ci) * Hc + gy) * Hc + gx];
            s_in[idx] = v;
        }
        for (int idx = tid; idx < CC * 9 * 8; idx += 448) {
            int ci = idx / 72; int k = (idx % 72) / 8; int co = idx % 8;
            s_w[idx] = w[((size_t)(coB + co) * Cin + (cc + ci)) * 9 + k];
        }
        __syncthreads();
        if (tid < 441) {
            #pragma unroll
            for (int ci = 0; ci < CC; ci++) {
                const float* si = &s_in[ci * 1936];
                #pragma unroll
                for (int k = 0; k < 9; k++) {
                    int dy = k / 3, dx = k % 3;
                    const float* p0 = si + (by + dy) * 44 + (bxp + dx);
                    float v00 = p0[0], v01 = p0[1], v10 = p0[44], v11 = p0[45];
                    float4 wA = *(const float4*)&s_w[(ci * 9 + k) * 8];
                    float4 wB = *(const float4*)&s_w[(ci * 9 + k) * 8 + 4];
                    float wv[8] = {wA.x, wA.y, wA.z, wA.w, wB.x, wB.y, wB.z, wB.w};
                    #pragma unroll
                    for (int j = 0; j < 8; j++) {
                        acc[j][0] += v00 * wv[j];
                        acc[j][1] += v01 * wv[j];
                        acc[j][2] += v10 * wv[j];
                        acc[j][3] += v11 * wv[j];
                    }
                }
            }
        }
        __syncthreads();
    }

    if (tid >= 441) return;
    int Hp = Hc >> 1;
    #pragma unroll
    for (int j = 0; j < 8; j++) {
        int co = coB + j;
        float m = fmaxf(fmaxf(acc[j][0], acc[j][1]), fmaxf(acc[j][2], acc[j][3]));
        m = fmaxf(m + bias[co], 0.0f);
        out[(((size_t)n * Cout + co) * Hp + ty) * Hp + tx] = m;
    }
}

// ---------------------------------------------------------------------------
// enc3: conv3x3 128->256 + bias + relu @21x21.
// 256 threads; thread = 2 adjacent pixels x 16 couts. Double-buffered smem.
// (round-3 variant: measured fma 44%, issue 69%, dur 1.197 ms)
// ---------------------------------------------------------------------------
__global__ void __launch_bounds__(256) k_enc3(
    const float* __restrict__ in, const float* __restrict__ w,
    const float* __restrict__ bias, float* __restrict__ out)
{
    const int CC = 8;
    __shared__ float s_in[2][CC * 529 + 8];
    __shared__ __align__(16) float s_w[2][CC * 9 * 16];

    const int coB = blockIdx.x * 16;
    const int n   = blockIdx.y;
    const int tid = threadIdx.x;
    const int y   = tid / 11;
    const int xp  = tid % 11;
    const int x0  = 2 * xp;
    const bool active = (tid < 231);
    const bool has2   = active && (xp < 10);

    float acc[2][16];
    #pragma unroll
    for (int p = 0; p < 2; p++)
        #pragma unroll
        for (int j = 0; j < 16; j++) acc[p][j] = 0.0f;

    const float* inN = in + (size_t)n * 128 * NP2;

    auto fill = [&](int bb, int cc) {
        #pragma unroll 1
        for (int idx = tid; idx < CC * 529; idx += 256) {
            int ci = idx / 529, rem = idx % 529;
            int r = rem / 23, c = rem % 23;
            int gy = r - 1, gx = c - 1;
            float v = 0.0f;
            if (gy >= 0 && gy < 21 && gx >= 0 && gx < 21)
                v = inN[(size_t)(cc + ci) * NP2 + gy * 21 + gx];
            s_in[bb][idx] = v;
        }
        #pragma unroll 1
        for (int idx = tid; idx < CC * 144; idx += 256) {
            int ci = idx / 144; int k = (idx % 144) / 16; int co = idx % 16;
            s_w[bb][idx] = w[((size_t)(coB + co) * 128 + (cc + ci)) * 9 + k];
        }
    };

    fill(0, 0);
    __syncthreads();

    for (int it = 0; it < 16; it++) {
        int bb = it & 1;
        if (it + 1 < 16) fill(bb ^ 1, (it + 1) * CC);
        if (active) {
            #pragma unroll
            for (int ci = 0; ci < CC; ci++) {
                const float* si = &s_in[bb][ci * 529 + y * 23 + x0];
                float v[3][4];
                #pragma unroll
                for (int r = 0; r < 3; r++) {
                    v[r][0] = si[r*23+0]; v[r][1] = si[r*23+1];
                    v[r][2] = si[r*23+2]; v[r][3] = si[r*23+3];
                }
                #pragma unroll
                for (int k = 0; k < 9; k++) {
                    const int dy = k / 3, dx = k % 3;
                    float v0 = v[dy][dx], v1 = v[dy][dx + 1];
                    const float* wb = &s_w[bb][(ci * 9 + k) * 16];
                    #pragma unroll
                    for (int q = 0; q < 4; q++) {
                        float4 wq = *(const float4*)(wb + q * 4);
                        acc[0][q*4+0] += v0 * wq.x;  acc[1][q*4+0] += v1 * wq.x;
                        acc[0][q*4+1] += v0 * wq.y;  acc[1][q*4+1] += v1 * wq.y;
                        acc[0][q*4+2] += v0 * wq.z;  acc[1][q*4+2] += v1 * wq.z;
                        acc[0][q*4+3] += v0 * wq.w;  acc[1][q*4+3] += v1 * wq.w;
                    }
                }
            }
        }
        __syncthreads();
    }

    if (!active) return;
    const int pix0 = y * 21 + x0;
    #pragma unroll
    for (int j = 0; j < 16; j++) {
        int co = coB + j;
        float bv = bias[co];
        float* op = &out[((size_t)n * 256 + co) * NP2 + pix0];
        op[0] = fmaxf(acc[0][j] + bv, 0.0f);
        if (has2) op[1] = fmaxf(acc[1][j] + bv, 0.0f);
    }
}

// ---------------------------------------------------------------------------
// decoder: FOLDED upsample(2x nearest)+conv3x3+bias+relu (round-2 version)
// ---------------------------------------------------------------------------
__global__ void __launch_bounds__(448) k_dec_up(
    const float* __restrict__ in, const float* __restrict__ w,
    const float* __restrict__ bias, float* __restrict__ out,
    int Cin, int Cout, int Hin, int nTilesX)
{
    const int CC = 8;
    __shared__ float s_in[CC * 529];
    __shared__ __align__(16) float s_fw[CC * 16 * 8];

    const int n   = blockIdx.z;
    const int coB = blockIdx.y * 8;
    const int tY  = blockIdx.x / nTilesX;
    const int tX  = blockIdx.x % nTilesX;
    const int y0  = tY * 21, x0 = tX * 21;
    const int tid = threadIdx.x;
    const int ty = tid / 21, tx = tid % 21;

    float acc[8][4];
    #pragma unroll
    for (int j = 0; j < 8; j++) { acc[j][0]=acc[j][1]=acc[j][2]=acc[j][3]=0.f; }

    const float* inN = in + (size_t)n * Cin * Hin * Hin;

    for (int cc = 0; cc < Cin; cc += CC) {
        for (int idx = tid; idx < CC * 529; idx += 448) {
            int ci = idx / 529, rem = idx % 529;
            int r = rem / 23, c = rem % 23;
            int gy = y0 - 1 + r, gx = x0 - 1 + c;
            float v = 0.0f;
            if (gy >= 0 && gy < Hin && gx >= 0 && gx < Hin)
                v = inN[((size_t)(cc + ci) * Hin + gy) * Hin + gx];
            s_in[idx] = v;
        }
        for (int idx = tid; idx < CC * 128; idx += 448) {
            int ci = idx >> 7;
            int pt = (idx >> 3) & 15;
            int co = idx & 7;
            int par = pt >> 2, tap = pt & 3;
            int py = par >> 1, px = par & 1, a = tap >> 1, b = tap & 1;
            const float* wb = &w[((size_t)(coB + co) * Cin + cc + ci) * 9];
            int rlo, rhi, clo, chi;
            if (py == 0) { if (a == 0) { rlo = 0; rhi = 0; } else { rlo = 1; rhi = 2; } }
            else         { if (a == 0) { rlo = 0; rhi = 1; } else { rlo = 2; rhi = 2; } }
            if (px == 0) { if (b == 0) { clo = 0; chi = 0; } else { clo = 1; chi = 2; } }
            else         { if (b == 0) { clo = 0; chi = 1; } else { clo = 2; chi = 2; } }
            float s = 0.0f;
            for (int r = rlo; r <= rhi; r++)
                for (int c = clo; c <= chi; c++)
                    s += wb[r * 3 + c];
            s_fw[idx] = s;
        }
        __syncthreads();
        if (tid < 441) {
            #pragma unroll
            for (int ci = 0; ci < CC; ci++) {
                const float* si = &s_in[ci * 529 + ty * 23 + tx];
                float v[3][3];
                #pragma unroll
                for (int r = 0; r < 3; r++) {
                    v[r][0] = si[r*23+0]; v[r][1] = si[r*23+1]; v[r][2] = si[r*23+2];
                }
                const float* fw = &s_fw[ci * 128];
                #pragma unroll
                for (int par = 0; par < 4; par++) {
                    const int py = par >> 1, px = par & 1;
                    #pragma unroll
                    for (int tap = 0; tap < 4; tap++) {
                        const int a = tap >> 1, b = tap & 1;
                        float vv = v[py + a][px + b];
                        float4 wA = *(const float4*)&fw[(par * 4 + tap) * 8];
                        float4 wB = *(const float4*)&fw[(par * 4 + tap) * 8 + 4];
                        acc[0][par] += vv * wA.x;  acc[1][par] += vv * wA.y;
                        acc[2][par] += vv * wA.z;  acc[3][par] += vv * wA.w;
                        acc[4][par] += vv * wB.x;  acc[5][par] += vv * wB.y;
                        acc[6][par] += vv * wB.z;  acc[7][par] += vv * wB.w;
                    }
                }
            }
        }
        __syncthreads();
    }

    if (tid >= 441) return;
    const int Hout = Hin * 2;
    #pragma unroll
    for (int j = 0; j < 8; j++) {
        int co = coB + j;
        float bv = bias[co];
        #pragma unroll
        for (int py = 0; py < 2; py++) {
            float2 o;
            o.x = fmaxf(acc[j][py * 2 + 0] + bv, 0.0f);
            o.y = fmaxf(acc[j][py * 2 + 1] + bv, 0.0f);
            size_t off = (((size_t)n * Cout + co) * Hout + (y0 + ty) * 2 + py) * Hout
                         + (size_t)(x0 + tx) * 2;
            *(float2*)&out[off] = o;
        }
    }
}

// ---------------------------------------------------------------------------
// depthwise conv 3x3 — feat half (channels 0..255), ALL frames, one launch
// ---------------------------------------------------------------------------
__global__ void __launch_bounds__(448) k_dw_feat(const float* __restrict__ dww)
{
    __shared__ float s[NP2];
    const int ch  = blockIdx.x;
    const int n   = blockIdx.y;
    const int tid = threadIdx.x;

    const float* src = &g_feat[((size_t)n * 256 + ch) * NP2];
    if (tid < NP2) s[tid] = src[tid];
    __syncthreads();
    if (tid >= NP2) return;

    float wr[9];
    #pragma unroll
    for (int k = 0; k < 9; k++) wr[k] = __ldg(&dww[(size_t)ch * 9 + k]);

    int y = tid / 21, x = tid % 21;
    float acc = 0.0f;
    #pragma unroll
    for (int k = 0; k < 9; k++) {
        int iy = y + k / 3 - 1, ix = x + k % 3 - 1;
        if (iy >= 0 && iy < 21 && ix >= 0 && ix < 21)
            acc += s[iy * 21 + ix] * wr[k];
    }
    g_gdwf[((size_t)n * 256 + ch) * NP2 + tid] = acc;
}

// depthwise conv — h half (channels 256..511), per step
__global__ void __launch_bounds__(448) k_dw_h(const float* __restrict__ dww)
{
    __shared__ float s[NP2];
    const int ch  = blockIdx.x;
    const int b   = blockIdx.y;
    const int tid = threadIdx.x;

    const float* src = &g_h[((size_t)b * HD + ch) * NP2];
    if (tid < NP2) s[tid] = src[tid];
    __syncthreads();
    if (tid >= NP2) return;

    float wr[9];
    #pragma unroll
    for (int k = 0; k < 9; k++) wr[k] = __ldg(&dww[(size_t)(256 + ch) * 9 + k]);

    int y = tid / 21, x = tid % 21;
    float acc = 0.0f;
    #pragma unroll
    for (int k = 0; k < 9; k++) {
        int iy = y + k / 3 - 1, ix = x + k % 3 - 1;
        if (iy >= 0 && iy < 21 && ix >= 0 && ix < 21)
            acc += s[iy * 21 + ix] * wr[k];
    }
    g_gdwh[((size_t)b * 256 + ch) * NP2 + tid] = acc;
}

// ---------------------------------------------------------------------------
// pw_feat: feat-half of pointwise conv for ALL frames (parallel, hoisted).
// pre[n][gate*256+cg][pix] = sum_{ci<256} W[gate*256+cg][ci] * gdwf[n][ci][pix]
// grid (32 co-groups, 128 frames), 448 threads; round-2 pw inner loop shape.
// ---------------------------------------------------------------------------
__global__ void __launch_bounds__(448) k_pw_feat(const float* __restrict__ pww)
{
    const int CC = 16;
    __shared__ float s_in[CC * NP2];
    __shared__ __align__(16) float s_w[CC * 32];

    const int coB = blockIdx.x * 8;
    const int n   = blockIdx.y;
    const int tid = threadIdx.x;

    float acc[32];
    #pragma unroll
    for (int j = 0; j < 32; j++) acc[j] = 0.0f;

    for (int cc = 0; cc < 256; cc += CC) {
        for (int idx = tid; idx < CC * NP2; idx += 448) {
            int ci = idx / NP2, p = idx % NP2;
            s_in[idx] = g_gdwf[((size_t)n * 256 + cc + ci) * NP2 + p];
        }
        for (int idx = tid; idx < CC * 32; idx += 448) {
            int ci = idx >> 5, j = idx & 31;
            int gate = j >> 3, co = j & 7;
            s_w[idx] = pww[((size_t)(gate * 256 + coB + co)) * 512 + cc + ci];
        }
        __syncthreads();
        if (tid < NP2) {
            #pragma unroll
            for (int ci = 0; ci < CC; ci++) {
                float v = s_in[ci * NP2 + tid];
                const float* fw = &s_w[ci * 32];
                #pragma unroll
                for (int q = 0; q < 8; q++) {
                    float4 wq = *(const float4*)(fw + q * 4);
                    acc[q*4+0] += v * wq.x;
                    acc[q*4+1] += v * wq.y;
                    acc[q*4+2] += v * wq.z;
                    acc[q*4+3] += v * wq.w;
                }
            }
        }
        __syncthreads();
    }

    if (tid >= NP2) return;
    #pragma unroll
    for (int j = 0; j < 32; j++) {
        int gate = j >> 3, co = j & 7;
        g_pre[((size_t)n * 1024 + gate * 256 + coB + co) * NP2 + tid] = acc[j];
    }
}

// ---------------------------------------------------------------------------
// pw_gates_h: h-half of pointwise (K=256) + precomputed feat-half + LSTM gates.
// grid (32 co-groups, 8 batch), 448 threads.
// ---------------------------------------------------------------------------
__global__ void __launch_bounds__(448) k_pw_gates_h(
    const float* __restrict__ pww, const float* __restrict__ pwb, int t)
{
    const int CC = 16;
    __shared__ float s_in[CC * NP2];
    __shared__ __align__(16) float s_w[CC * 32];

    const int coB = blockIdx.x * 8;
    const int b   = blockIdx.y;
    const int tid = threadIdx.x;

    float acc[32];
    #pragma unroll
    for (int j = 0; j < 32; j++) acc[j] = 0.0f;

    for (int cc = 0; cc < 256; cc += CC) {
        for (int idx = tid; idx < CC * NP2; idx += 448) {
            int ci = idx / NP2, p = idx % NP2;
            s_in[idx] = g_gdwh[((size_t)b * 256 + cc + ci) * NP2 + p];
        }
        for (int idx = tid; idx < CC * 32; idx += 448) {
            int ci = idx >> 5, j = idx & 31;
            int gate = j >> 3, co = j & 7;
            s_w[idx] = pww[((size_t)(gate * 256 + coB + co)) * 512 + 256 + cc + ci];
        }
        __syncthreads();
        if (tid < NP2) {
            #pragma unroll
            for (int ci = 0; ci < CC; ci++) {
                float v = s_in[ci * NP2 + tid];
                const float* fw = &s_w[ci * 32];
                #pragma unroll
                for (int q = 0; q < 8; q++) {
                    float4 wq = *(const float4*)(fw + q * 4);
                    acc[q*4+0] += v * wq.x;
                    acc[q*4+1] += v * wq.y;
                    acc[q*4+2] += v * wq.z;
                    acc[q*4+3] += v * wq.w;
                }
            }
        }
        __syncthreads();
    }

    if (tid >= NP2) return;
    const int n = b * TT + t;
    #pragma unroll
    for (int co = 0; co < 8; co++) {
        int cg = coB + co;
        const float* pre = &g_pre[(size_t)n * 1024 * NP2];
        float ia = acc[co]      + pre[((size_t)0 * 256 + cg) * NP2 + tid];
        float fa = acc[8 + co]  + pre[((size_t)1 * 256 + cg) * NP2 + tid];
        float oa = acc[16 + co] + pre[((size_t)2 * 256 + cg) * NP2 + tid];
        float ga = acc[24 + co] + pre[((size_t)3 * 256 + cg) * NP2 + tid];
        float iv = sigm(ia + pwb[cg]);
        float fv = sigm(fa + pwb[256 + cg]);
        float ov = sigm(oa + pwb[512 + cg]);
        float gv = tanhf(ga + pwb[768 + cg]);
        size_t off = ((size_t)b * HD + cg) * NP2 + tid;
        float c2 = fv * g_c[off] + iv * gv;
        float h2 = ov * tanhf(c2);
        g_c[off] = c2;
        g_h[off] = h2;
        g_hs[((size_t)n * 256 + cg) * NP2 + tid] = h2;
    }
}

// ---------------------------------------------------------------------------
// dec3: 1x1 conv 64->1 + bias.
// ---------------------------------------------------------------------------
__global__ void k_dec3(const float* __restrict__ w, const float* __restrict__ bias,
                       float* __restrict__ out)
{
    __shared__ float s_w[64];
    if (threadIdx.x < 64) s_w[threadIdx.x] = w[threadIdx.x];
    __syncthreads();

    int idx = blockIdx.x * blockDim.x + threadIdx.x;
    if (idx >= OUTN) return;
    int n = idx / NP0, pix = idx % NP0;
    const float* d = &g_d2[(size_t)n * 64 * NP0 + pix];
    float acc = bias[0];
    #pragma unroll
    for (int c = 0; c < 64; c++) acc += d[(size_t)c * NP0] * s_w[c];
    out[idx] = acc;
}

__global__ void k_copy_hc(float* __restrict__ out)
{
    int i = blockIdx.x * blockDim.x + threadIdx.x;
    if (i < BB * HD * NP2) {
        out[OUTN + i]     = g_h[i];
        out[2 * OUTN + i] = g_c[i];
    }
}

// ---------------------------------------------------------------------------
extern "C" void kernel_launch(void* const* d_in, const int* in_sizes, int n_in,
                              void* d_out, int out_size)
{
    const float* x      = (const float*)d_in[0];
    const float* enc_w1 = (const float*)d_in[1];
    const float* enc_b1 = (const float*)d_in[2];
    const float* enc_w2 = (const float*)d_in[3];
    const float* enc_b2 = (const float*)d_in[4];
    const float* enc_w3 = (const float*)d_in[5];
    const float* enc_b3 = (const float*)d_in[6];
    const float* dw_w   = (const float*)d_in[7];
    const float* pw_w   = (const float*)d_in[8];
    const float* pw_b   = (const float*)d_in[9];
    const float* dec_w1 = (const float*)d_in[10];
    const float* dec_b1 = (const float*)d_in[11];
    const float* dec_w2 = (const float*)d_in[12];
    const float* dec_b2 = (const float*)d_in[13];
    const float* dec_w3 = (const float*)d_in[14];
    const float* dec_b3 = (const float*)d_in[15];
    float* out = (float*)d_out;

    float *e1, *e2, *feat, *hs, *d1, *d2;
    cudaGetSymbolAddress((void**)&e1,   g_e1);
    cudaGetSymbolAddress((void**)&e2,   g_e2);
    cudaGetSymbolAddress((void**)&feat, g_feat);
    cudaGetSymbolAddress((void**)&hs,   g_hs);
    cudaGetSymbolAddress((void**)&d1,   g_d1);
    cudaGetSymbolAddress((void**)&d2,   g_d2);

    k_zero_hc<<<(BB * HD * NP2 + 255) / 256, 256>>>();

    // encoder
    k_enc1<<<dim3(4, 1, BT), 448>>>(x, enc_w1, enc_b1, e1);
    k_conv_pool<<<dim3(1, 128 / 8, BT), 448>>>(e1, enc_w2, enc_b2, e2, 64, 128, 42);
    k_enc3<<<dim3(256 / 16, BT), 256>>>(e2, enc_w3, enc_b3, feat);

    // hoisted h-independent work: depthwise(feat) and feat-half of pointwise
    k_dw_feat<<<dim3(256, BT), 448>>>(dw_w);
    k_pw_feat<<<dim3(32, BT), 448>>>(pw_w);

    // ConvLSTM over T=16 steps — only h-dependent half on the critical path
    for (int t = 0; t < TT; t++) {
        k_dw_h<<<dim3(256, BB), 448>>>(dw_w);
        k_pw_gates_h<<<dim3(32, BB), 448>>>(pw_w, pw_b, t);
    }

    // decoder with folded nearest-upsample conv
    k_dec_up<<<dim3(1, 128 / 8, BT), 448>>>(hs, dec_w1, dec_b1, d1, 256, 128, 21, 1);
    k_dec_up<<<dim3(4, 64 / 8, BT), 448>>>(d1, dec_w2, dec_b2, d2, 128, 64, 42, 2);
    k_dec3<<<(OUTN + 255) / 256, 256>>>(dec_w3, dec_b3, out);

    if (out_size >= 3 * OUTN)
        k_copy_hc<<<(BB * HD * NP2 + 255) / 256, 256>>>(out);
}

// round 6
// speedup vs baseline: 1.2994x; 1.0026x over previous
#include <cuda_runtime.h>
#include <cuda_bf16.h>
#include <math.h>

// ---------------------------------------------------------------------------
//   x: (8,16,3,84,84)  B=8 T=16  -> BT=128 frames
//   enc: 3->64 (pool), 64->128 (pool), 128->256    @84/42/21
//   ConvLSTM: depthwise 3x3 g=512, pointwise 512->1024, gates
//   dec: up2 conv 256->128 @42, up2 conv 128->64 @84, 1x1 64->1
// ---------------------------------------------------------------------------

#define BT   128
#define BB   8
#define TT   16
#define HD   256
#define NP2  441
#define NP1  1764
#define NP0  7056
#define OUTN 903168

__device__ float g_e1  [BT * 64  * NP1];
__device__ float g_e2  [BT * 128 * NP2];
__device__ float g_feat[BT * 256 * NP2];
__device__ float g_gdwf[BT * 256 * NP2];   // depthwise(feat), all frames
__device__ float g_gdwh[BB * 256 * NP2];   // depthwise(h), current step
__device__ float g_pre [BT * 1024 * NP2];  // feat-half of pointwise gates, all frames
__device__ float g_hs  [BT * 256 * NP2];
__device__ float g_d1  [BT * 128 * NP1];
__device__ float g_d2  [BT * 64  * NP0];
__device__ float g_h   [BB * HD * NP2];
__device__ float g_c   [BB * HD * NP2];

__device__ __forceinline__ float sigm(float x) { return 1.0f / (1.0f + expf(-x)); }

__global__ void k_zero_hc()
{
    int i = blockIdx.x * blockDim.x + threadIdx.x;
    if (i < BB * HD * NP2) { g_h[i] = 0.0f; g_c[i] = 0.0f; }
}

// ---------------------------------------------------------------------------
// enc1: conv3x3 3->64 + bias + relu + maxpool2.  84x84 -> pooled 42x42
// ---------------------------------------------------------------------------
__global__ void __launch_bounds__(448) k_enc1(
    const float* __restrict__ x, const float* __restrict__ w,
    const float* __restrict__ bias, float* __restrict__ out)
{
    __shared__ float s_in[3 * 44 * 44];
    __shared__ __align__(16) float s_w[3 * 9 * 64];

    const int n   = blockIdx.z;
    const int bx  = blockIdx.x;
    const int py0 = (bx >> 1) * 21;
    const int px0 = (bx & 1) * 21;
    const int oy0 = py0 * 2;
    const int ox0 = px0 * 2;
    const int tid = threadIdx.x;

    const float* xn = x + (size_t)n * 3 * NP0;

    for (int idx = tid; idx < 3 * 44 * 44; idx += 448) {
        int ci = idx / 1936, rem = idx % 1936;
        int r = rem / 44, c = rem % 44;
        int gy = oy0 - 1 + r, gx = ox0 - 1 + c;
        float v = 0.0f;
        if (gy >= 0 && gy < 84 && gx >= 0 && gx < 84)
            v = xn[(size_t)ci * NP0 + gy * 84 + gx];
        s_in[idx] = v;
    }
    for (int idx = tid; idx < 3 * 9 * 64; idx += 448) {
        int ci = idx / (9 * 64); int k = (idx % (9 * 64)) / 64; int co = idx % 64;
        s_w[idx] = w[((size_t)co * 3 + ci) * 9 + k];
    }
    __syncthreads();
    if (tid >= 441) return;

    const int ty = tid / 21, tx = tid % 21;
    const int by = 2 * ty, bxp = 2 * tx;

    for (int cg = 0; cg < 8; cg++) {
        float acc[8][4];
        #pragma unroll
        for (int j = 0; j < 8; j++) { acc[j][0]=acc[j][1]=acc[j][2]=acc[j][3]=0.f; }
        #pragma unroll
        for (int ci = 0; ci < 3; ci++) {
            const float* si = &s_in[ci * 1936];
            #pragma unroll
            for (int k = 0; k < 9; k++) {
                int dy = k / 3, dx = k % 3;
                const float* p0 = si + (by + dy) * 44 + (bxp + dx);
                float v00 = p0[0], v01 = p0[1], v10 = p0[44], v11 = p0[45];
                float4 wA = *(const float4*)&s_w[(ci * 9 + k) * 64 + cg * 8];
                float4 wB = *(const float4*)&s_w[(ci * 9 + k) * 64 + cg * 8 + 4];
                float wv[8] = {wA.x, wA.y, wA.z, wA.w, wB.x, wB.y, wB.z, wB.w};
                #pragma unroll
                for (int j = 0; j < 8; j++) {
                    acc[j][0] += v00 * wv[j];
                    acc[j][1] += v01 * wv[j];
                    acc[j][2] += v10 * wv[j];
                    acc[j][3] += v11 * wv[j];
                }
            }
        }
        #pragma unroll
        for (int j = 0; j < 8; j++) {
            int co = cg * 8 + j;
            float m = fmaxf(fmaxf(acc[j][0], acc[j][1]), fmaxf(acc[j][2], acc[j][3]));
            m = fmaxf(m + bias[co], 0.0f);
            out[(((size_t)n * 64 + co) * 42 + py0 + ty) * 42 + px0 + tx] = m;
        }
    }
}

// ---------------------------------------------------------------------------
// enc2: conv3x3 64->128 + bias + relu + maxpool2 @42 -> 21 (round-2 version)
// ---------------------------------------------------------------------------
__global__ void __launch_bounds__(448) k_conv_pool(
    const float* __restrict__ in, const float* __restrict__ w,
    const float* __restrict__ bias, float* __restrict__ out,
    int Cin, int Cout, int Hc)
{
    const int CC = 4;
    __shared__ float s_in[CC * 44 * 44];
    __shared__ __align__(16) float s_w[CC * 9 * 8];

    const int n   = blockIdx.z;
    const int coB = blockIdx.y * 8;
    const int tid = threadIdx.x;
    const int ty = tid / 21, tx = tid % 21;
    const int by = 2 * ty, bxp = 2 * tx;

    float acc[8][4];
    #pragma unroll
    for (int j = 0; j < 8; j++) { acc[j][0]=acc[j][1]=acc[j][2]=acc[j][3]=0.f; }

    const float* inN = in + (size_t)n * Cin * Hc * Hc;

    for (int cc = 0; cc < Cin; cc += CC) {
        for (int idx = tid; idx < CC * 44 * 44; idx += 448) {
            int ci = idx / 1936, rem = idx % 1936;
            int r = rem / 44, c = rem % 44;
            int gy = r - 1, gx = c - 1;
            float v = 0.0f;
            if (gy >= 0 && gy < Hc && gx >= 0 && gx < Hc)
                v = inN[((size_t)(cc + ci) * Hc + gy) * Hc + gx];
            s_in[idx] = v;
        }
        for (int idx = tid; idx < CC * 9 * 8; idx += 448) {
            int ci = idx / 72; int k = (idx % 72) / 8; int co = idx % 8;
            s_w[idx] = w[((size_t)(coB + co) * Cin + (cc + ci)) * 9 + k];
        }
        __syncthreads();
        if (tid < 441) {
            #pragma unroll
            for (int ci = 0; ci < CC; ci++) {
                const float* si = &s_in[ci * 1936];
                #pragma unroll
                for (int k = 0; k < 9; k++) {
                    int dy = k / 3, dx = k % 3;
                    const float* p0 = si + (by + dy) * 44 + (bxp + dx);
                    float v00 = p0[0], v01 = p0[1], v10 = p0[44], v11 = p0[45];
                    float4 wA = *(const float4*)&s_w[(ci * 9 + k) * 8];
                    float4 wB = *(const float4*)&s_w[(ci * 9 + k) * 8 + 4];
                    float wv[8] = {wA.x, wA.y, wA.z, wA.w, wB.x, wB.y, wB.z, wB.w};
                    #pragma unroll
                    for (int j = 0; j < 8; j++) {
                        acc[j][0] += v00 * wv[j];
                        acc[j][1] += v01 * wv[j];
                        acc[j][2] += v10 * wv[j];
                        acc[j][3] += v11 * wv[j];
                    }
                }
            }
        }
        __syncthreads();
    }

    if (tid >= 441) return;
    int Hp = Hc >> 1;
    #pragma unroll
    for (int j = 0; j < 8; j++) {
        int co = coB + j;
        float m = fmaxf(fmaxf(acc[j][0], acc[j][1]), fmaxf(acc[j][2], acc[j][3]));
        m = fmaxf(m + bias[co], 0.0f);
        out[(((size_t)n * Cout + co) * Hp + ty) * Hp + tx] = m;
    }
}

// ---------------------------------------------------------------------------
// enc3: conv3x3 128->256 + bias + relu @21x21.
// 256 threads; thread = 2 adjacent pixels x 16 couts. Double-buffered smem.
// (round-3 variant: measured fma 44%, issue 69%, dur 1.197 ms)
// ---------------------------------------------------------------------------
__global__ void __launch_bounds__(256) k_enc3(
    const float* __restrict__ in, const float* __restrict__ w,
    const float* __restrict__ bias, float* __restrict__ out)
{
    const int CC = 8;
    __shared__ float s_in[2][CC * 529 + 8];
    __shared__ __align__(16) float s_w[2][CC * 9 * 16];

    const int coB = blockIdx.x * 16;
    const int n   = blockIdx.y;
    const int tid = threadIdx.x;
    const int y   = tid / 11;
    const int xp  = tid % 11;
    const int x0  = 2 * xp;
    const bool active = (tid < 231);
    const bool has2   = active && (xp < 10);

    float acc[2][16];
    #pragma unroll
    for (int p = 0; p < 2; p++)
        #pragma unroll
        for (int j = 0; j < 16; j++) acc[p][j] = 0.0f;

    const float* inN = in + (size_t)n * 128 * NP2;

    auto fill = [&](int bb, int cc) {
        #pragma unroll 1
        for (int idx = tid; idx < CC * 529; idx += 256) {
            int ci = idx / 529, rem = idx % 529;
            int r = rem / 23, c = rem % 23;
            int gy = r - 1, gx = c - 1;
            float v = 0.0f;
            if (gy >= 0 && gy < 21 && gx >= 0 && gx < 21)
                v = inN[(size_t)(cc + ci) * NP2 + gy * 21 + gx];
            s_in[bb][idx] = v;
        }
        #pragma unroll 1
        for (int idx = tid; idx < CC * 144; idx += 256) {
            int ci = idx / 144; int k = (idx % 144) / 16; int co = idx % 16;
            s_w[bb][idx] = w[((size_t)(coB + co) * 128 + (cc + ci)) * 9 + k];
        }
    };

    fill(0, 0);
    __syncthreads();

    for (int it = 0; it < 16; it++) {
        int bb = it & 1;
        if (it + 1 < 16) fill(bb ^ 1, (it + 1) * CC);
        if (active) {
            #pragma unroll
            for (int ci = 0; ci < CC; ci++) {
                const float* si = &s_in[bb][ci * 529 + y * 23 + x0];
                float v[3][4];
                #pragma unroll
                for (int r = 0; r < 3; r++) {
                    v[r][0] = si[r*23+0]; v[r][1] = si[r*23+1];
                    v[r][2] = si[r*23+2]; v[r][3] = si[r*23+3];
                }
                #pragma unroll
                for (int k = 0; k < 9; k++) {
                    const int dy = k / 3, dx = k % 3;
                    float v0 = v[dy][dx], v1 = v[dy][dx + 1];
                    const float* wb = &s_w[bb][(ci * 9 + k) * 16];
                    #pragma unroll
                    for (int q = 0; q < 4; q++) {
                        float4 wq = *(const float4*)(wb + q * 4);
                        acc[0][q*4+0] += v0 * wq.x;  acc[1][q*4+0] += v1 * wq.x;
                        acc[0][q*4+1] += v0 * wq.y;  acc[1][q*4+1] += v1 * wq.y;
                        acc[0][q*4+2] += v0 * wq.z;  acc[1][q*4+2] += v1 * wq.z;
                        acc[0][q*4+3] += v0 * wq.w;  acc[1][q*4+3] += v1 * wq.w;
                    }
                }
            }
        }
        __syncthreads();
    }

    if (!active) return;
    const int pix0 = y * 21 + x0;
    #pragma unroll
    for (int j = 0; j < 16; j++) {
        int co = coB + j;
        float bv = bias[co];
        float* op = &out[((size_t)n * 256 + co) * NP2 + pix0];
        op[0] = fmaxf(acc[0][j] + bv, 0.0f);
        if (has2) op[1] = fmaxf(acc[1][j] + bv, 0.0f);
    }
}

// ---------------------------------------------------------------------------
// decoder: FOLDED upsample(2x nearest)+conv3x3+bias+relu (round-2 version)
// ---------------------------------------------------------------------------
__global__ void __launch_bounds__(448) k_dec_up(
    const float* __restrict__ in, const float* __restrict__ w,
    const float* __restrict__ bias, float* __restrict__ out,
    int Cin, int Cout, int Hin, int nTilesX)
{
    const int CC = 8;
    __shared__ float s_in[CC * 529];
    __shared__ __align__(16) float s_fw[CC * 16 * 8];

    const int n   = blockIdx.z;
    const int coB = blockIdx.y * 8;
    const int tY  = blockIdx.x / nTilesX;
    const int tX  = blockIdx.x % nTilesX;
    const int y0  = tY * 21, x0 = tX * 21;
    const int tid = threadIdx.x;
    const int ty = tid / 21, tx = tid % 21;

    float acc[8][4];
    #pragma unroll
    for (int j = 0; j < 8; j++) { acc[j][0]=acc[j][1]=acc[j][2]=acc[j][3]=0.f; }

    const float* inN = in + (size_t)n * Cin * Hin * Hin;

    for (int cc = 0; cc < Cin; cc += CC) {
        for (int idx = tid; idx < CC * 529; idx += 448) {
            int ci = idx / 529, rem = idx % 529;
            int r = rem / 23, c = rem % 23;
            int gy = y0 - 1 + r, gx = x0 - 1 + c;
            float v = 0.0f;
            if (gy >= 0 && gy < Hin && gx >= 0 && gx < Hin)
                v = inN[((size_t)(cc + ci) * Hin + gy) * Hin + gx];
            s_in[idx] = v;
        }
        for (int idx = tid; idx < CC * 128; idx += 448) {
            int ci = idx >> 7;
            int pt = (idx >> 3) & 15;
            int co = idx & 7;
            int par = pt >> 2, tap = pt & 3;
            int py = par >> 1, px = par & 1, a = tap >> 1, b = tap & 1;
            const float* wb = &w[((size_t)(coB + co) * Cin + cc + ci) * 9];
            int rlo, rhi, clo, chi;
            if (py == 0) { if (a == 0) { rlo = 0; rhi = 0; } else { rlo = 1; rhi = 2; } }
            else         { if (a == 0) { rlo = 0; rhi = 1; } else { rlo = 2; rhi = 2; } }
            if (px == 0) { if (b == 0) { clo = 0; chi = 0; } else { clo = 1; chi = 2; } }
            else         { if (b == 0) { clo = 0; chi = 1; } else { clo = 2; chi = 2; } }
            float s = 0.0f;
            for (int r = rlo; r <= rhi; r++)
                for (int c = clo; c <= chi; c++)
                    s += wb[r * 3 + c];
            s_fw[idx] = s;
        }
        __syncthreads();
        if (tid < 441) {
            #pragma unroll
            for (int ci = 0; ci < CC; ci++) {
                const float* si = &s_in[ci * 529 + ty * 23 + tx];
                float v[3][3];
                #pragma unroll
                for (int r = 0; r < 3; r++) {
                    v[r][0] = si[r*23+0]; v[r][1] = si[r*23+1]; v[r][2] = si[r*23+2];
                }
                const float* fw = &s_fw[ci * 128];
                #pragma unroll
                for (int par = 0; par < 4; par++) {
                    const int py = par >> 1, px = par & 1;
                    #pragma unroll
                    for (int tap = 0; tap < 4; tap++) {
                        const int a = tap >> 1, b = tap & 1;
                        float vv = v[py + a][px + b];
                        float4 wA = *(const float4*)&fw[(par * 4 + tap) * 8];
                        float4 wB = *(const float4*)&fw[(par * 4 + tap) * 8 + 4];
                        acc[0][par] += vv * wA.x;  acc[1][par] += vv * wA.y;
                        acc[2][par] += vv * wA.z;  acc[3][par] += vv * wA.w;
                        acc[4][par] += vv * wB.x;  acc[5][par] += vv * wB.y;
                        acc[6][par] += vv * wB.z;  acc[7][par] += vv * wB.w;
                    }
                }
            }
        }
        __syncthreads();
    }

    if (tid >= 441) return;
    const int Hout = Hin * 2;
    #pragma unroll
    for (int j = 0; j < 8; j++) {
        int co = coB + j;
        float bv = bias[co];
        #pragma unroll
        for (int py = 0; py < 2; py++) {
            float2 o;
            o.x = fmaxf(acc[j][py * 2 + 0] + bv, 0.0f);
            o.y = fmaxf(acc[j][py * 2 + 1] + bv, 0.0f);
            size_t off = (((size_t)n * Cout + co) * Hout + (y0 + ty) * 2 + py) * Hout
                         + (size_t)(x0 + tx) * 2;
            *(float2*)&out[off] = o;
        }
    }
}

// ---------------------------------------------------------------------------
// depthwise conv 3x3 — feat half (channels 0..255), ALL frames, one launch
// ---------------------------------------------------------------------------
__global__ void __launch_bounds__(448) k_dw_feat(const float* __restrict__ dww)
{
    __shared__ float s[NP2];
    const int ch  = blockIdx.x;
    const int n   = blockIdx.y;
    const int tid = threadIdx.x;

    const float* src = &g_feat[((size_t)n * 256 + ch) * NP2];
    if (tid < NP2) s[tid] = src[tid];
    __syncthreads();
    if (tid >= NP2) return;

    float wr[9];
    #pragma unroll
    for (int k = 0; k < 9; k++) wr[k] = __ldg(&dww[(size_t)ch * 9 + k]);

    int y = tid / 21, x = tid % 21;
    float acc = 0.0f;
    #pragma unroll
    for (int k = 0; k < 9; k++) {
        int iy = y + k / 3 - 1, ix = x + k % 3 - 1;
        if (iy >= 0 && iy < 21 && ix >= 0 && ix < 21)
            acc += s[iy * 21 + ix] * wr[k];
    }
    g_gdwf[((size_t)n * 256 + ch) * NP2 + tid] = acc;
}

// depthwise conv — h half (channels 256..511), per step
__global__ void __launch_bounds__(448) k_dw_h(const float* __restrict__ dww)
{
    __shared__ float s[NP2];
    const int ch  = blockIdx.x;
    const int b   = blockIdx.y;
    const int tid = threadIdx.x;

    const float* src = &g_h[((size_t)b * HD + ch) * NP2];
    if (tid < NP2) s[tid] = src[tid];
    __syncthreads();
    if (tid >= NP2) return;

    float wr[9];
    #pragma unroll
    for (int k = 0; k < 9; k++) wr[k] = __ldg(&dww[(size_t)(256 + ch) * 9 + k]);

    int y = tid / 21, x = tid % 21;
    float acc = 0.0f;
    #pragma unroll
    for (int k = 0; k < 9; k++) {
        int iy = y + k / 3 - 1, ix = x + k % 3 - 1;
        if (iy >= 0 && iy < 21 && ix >= 0 && ix < 21)
            acc += s[iy * 21 + ix] * wr[k];
    }
    g_gdwh[((size_t)b * 256 + ch) * NP2 + tid] = acc;
}

// ---------------------------------------------------------------------------
// pw_feat: feat-half of pointwise conv for ALL frames (parallel, hoisted).
// pre[n][gate*256+cg][pix] = sum_{ci<256} W[gate*256+cg][ci] * gdwf[n][ci][pix]
// grid (32 co-groups, 128 frames), 448 threads; round-2 pw inner loop shape.
// ---------------------------------------------------------------------------
__global__ void __launch_bounds__(448) k_pw_feat(const float* __restrict__ pww)
{
    const int CC = 16;
    __shared__ float s_in[CC * NP2];
    __shared__ __align__(16) float s_w[CC * 32];

    const int coB = blockIdx.x * 8;
    const int n   = blockIdx.y;
    const int tid = threadIdx.x;

    float acc[32];
    #pragma unroll
    for (int j = 0; j < 32; j++) acc[j] = 0.0f;

    for (int cc = 0; cc < 256; cc += CC) {
        for (int idx = tid; idx < CC * NP2; idx += 448) {
            int ci = idx / NP2, p = idx % NP2;
            s_in[idx] = g_gdwf[((size_t)n * 256 + cc + ci) * NP2 + p];
        }
        for (int idx = tid; idx < CC * 32; idx += 448) {
            int ci = idx >> 5, j = idx & 31;
            int gate = j >> 3, co = j & 7;
            s_w[idx] = pww[((size_t)(gate * 256 + coB + co)) * 512 + cc + ci];
        }
        __syncthreads();
        if (tid < NP2) {
            #pragma unroll
            for (int ci = 0; ci < CC; ci++) {
                float v = s_in[ci * NP2 + tid];
                const float* fw = &s_w[ci * 32];
                #pragma unroll
                for (int q = 0; q < 8; q++) {
                    float4 wq = *(const float4*)(fw + q * 4);
                    acc[q*4+0] += v * wq.x;
                    acc[q*4+1] += v * wq.y;
                    acc[q*4+2] += v * wq.z;
                    acc[q*4+3] += v * wq.w;
                }
            }
        }
        __syncthreads();
    }

    if (tid >= NP2) return;
    #pragma unroll
    for (int j = 0; j < 32; j++) {
        int gate = j >> 3, co = j & 7;
        g_pre[((size_t)n * 1024 + gate * 256 + coB + co) * NP2 + tid] = acc[j];
    }
}

// ---------------------------------------------------------------------------
// pw_gates_h: h-half of pointwise (K=256) + precomputed feat-half + LSTM gates.
// grid (32 co-groups, 8 batch), 448 threads.
// ---------------------------------------------------------------------------
__global__ void __launch_bounds__(448) k_pw_gates_h(
    const float* __restrict__ pww, const float* __restrict__ pwb, int t)
{
    const int CC = 16;
    __shared__ float s_in[CC * NP2];
    __shared__ __align__(16) float s_w[CC * 32];

    const int coB = blockIdx.x * 8;
    const int b   = blockIdx.y;
    const int tid = threadIdx.x;

    float acc[32];
    #pragma unroll
    for (int j = 0; j < 32; j++) acc[j] = 0.0f;

    for (int cc = 0; cc < 256; cc += CC) {
        for (int idx = tid; idx < CC * NP2; idx += 448) {
            int ci = idx / NP2, p = idx % NP2;
            s_in[idx] = g_gdwh[((size_t)b * 256 + cc + ci) * NP2 + p];
        }
        for (int idx = tid; idx < CC * 32; idx += 448) {
            int ci = idx >> 5, j = idx & 31;
            int gate = j >> 3, co = j & 7;
            s_w[idx] = pww[((size_t)(gate * 256 + coB + co)) * 512 + 256 + cc + ci];
        }
        __syncthreads();
        if (tid < NP2) {
            #pragma unroll
            for (int ci = 0; ci < CC; ci++) {
                float v = s_in[ci * NP2 + tid];
                const float* fw = &s_w[ci * 32];
                #pragma unroll
                for (int q = 0; q < 8; q++) {
                    float4 wq = *(const float4*)(fw + q * 4);
                    acc[q*4+0] += v * wq.x;
                    acc[q*4+1] += v * wq.y;
                    acc[q*4+2] += v * wq.z;
                    acc[q*4+3] += v * wq.w;
                }
            }
        }
        __syncthreads();
    }

    if (tid >= NP2) return;
    const int n = b * TT + t;
    #pragma unroll
    for (int co = 0; co < 8; co++) {
        int cg = coB + co;
        const float* pre = &g_pre[(size_t)n * 1024 * NP2];
        float ia = acc[co]      + pre[((size_t)0 * 256 + cg) * NP2 + tid];
        float fa = acc[8 + co]  + pre[((size_t)1 * 256 + cg) * NP2 + tid];
        float oa = acc[16 + co] + pre[((size_t)2 * 256 + cg) * NP2 + tid];
        float ga = acc[24 + co] + pre[((size_t)3 * 256 + cg) * NP2 + tid];
        float iv = sigm(ia + pwb[cg]);
        float fv = sigm(fa + pwb[256 + cg]);
        float ov = sigm(oa + pwb[512 + cg]);
        float gv = tanhf(ga + pwb[768 + cg]);
        size_t off = ((size_t)b * HD + cg) * NP2 + tid;
        float c2 = fv * g_c[off] + iv * gv;
        float h2 = ov * tanhf(c2);
        g_c[off] = c2;
        g_h[off] = h2;
        g_hs[((size_t)n * 256 + cg) * NP2 + tid] = h2;
    }
}

// ---------------------------------------------------------------------------
// dec3: 1x1 conv 64->1 + bias.
// ---------------------------------------------------------------------------
__global__ void k_dec3(const float* __restrict__ w, const float* __restrict__ bias,
                       float* __restrict__ out)
{
    __shared__ float s_w[64];
    if (threadIdx.x < 64) s_w[threadIdx.x] = w[threadIdx.x];
    __syncthreads();

    int idx = blockIdx.x * blockDim.x + threadIdx.x;
    if (idx >= OUTN) return;
    int n = idx / NP0, pix = idx % NP0;
    const float* d = &g_d2[(size_t)n * 64 * NP0 + pix];
    float acc = bias[0];
    #pragma unroll
    for (int c = 0; c < 64; c++) acc += d[(size_t)c * NP0] * s_w[c];
    out[idx] = acc;
}

__global__ void k_copy_hc(float* __restrict__ out)
{
    int i = blockIdx.x * blockDim.x + threadIdx.x;
    if (i < BB * HD * NP2) {
        out[OUTN + i]     = g_h[i];
        out[2 * OUTN + i] = g_c[i];
    }
}

// ---------------------------------------------------------------------------
extern "C" void kernel_launch(void* const* d_in, const int* in_sizes, int n_in,
                              void* d_out, int out_size)
{
    const float* x      = (const float*)d_in[0];
    const float* enc_w1 = (const float*)d_in[1];
    const float* enc_b1 = (const float*)d_in[2];
    const float* enc_w2 = (const float*)d_in[3];
    const float* enc_b2 = (const float*)d_in[4];
    const float* enc_w3 = (const float*)d_in[5];
    const float* enc_b3 = (const float*)d_in[6];
    const float* dw_w   = (const float*)d_in[7];
    const float* pw_w   = (const float*)d_in[8];
    const float* pw_b   = (const float*)d_in[9];
    const float* dec_w1 = (const float*)d_in[10];
    const float* dec_b1 = (const float*)d_in[11];
    const float* dec_w2 = (const float*)d_in[12];
    const float* dec_b2 = (const float*)d_in[13];
    const float* dec_w3 = (const float*)d_in[14];
    const float* dec_b3 = (const float*)d_in[15];
    float* out = (float*)d_out;

    float *e1, *e2, *feat, *hs, *d1, *d2;
    cudaGetSymbolAddress((void**)&e1,   g_e1);
    cudaGetSymbolAddress((void**)&e2,   g_e2);
    cudaGetSymbolAddress((void**)&feat, g_feat);
    cudaGetSymbolAddress((void**)&hs,   g_hs);
    cudaGetSymbolAddress((void**)&d1,   g_d1);
    cudaGetSymbolAddress((void**)&d2,   g_d2);

    k_zero_hc<<<(BB * HD * NP2 + 255) / 256, 256>>>();

    // encoder
    k_enc1<<<dim3(4, 1, BT), 448>>>(x, enc_w1, enc_b1, e1);
    k_conv_pool<<<dim3(1, 128 / 8, BT), 448>>>(e1, enc_w2, enc_b2, e2, 64, 128, 42);
    k_enc3<<<dim3(256 / 16, BT), 256>>>(e2, enc_w3, enc_b3, feat);

    // hoisted h-independent work: depthwise(feat) and feat-half of pointwise
    k_dw_feat<<<dim3(256, BT), 448>>>(dw_w);
    k_pw_feat<<<dim3(32, BT), 448>>>(pw_w);

    // ConvLSTM over T=16 steps — only h-dependent half on the critical path
    for (int t = 0; t < TT; t++) {
        k_dw_h<<<dim3(256, BB), 448>>>(dw_w);
        k_pw_gates_h<<<dim3(32, BB), 448>>>(pw_w, pw_b, t);
    }

    // decoder with folded nearest-upsample conv
    k_dec_up<<<dim3(1, 128 / 8, BT), 448>>>(hs, dec_w1, dec_b1, d1, 256, 128, 21, 1);
    k_dec_up<<<dim3(4, 64 / 8, BT), 448>>>(d1, dec_w2, dec_b2, d2, 128, 64, 42, 2);
    k_dec3<<<(OUTN + 255) / 256, 256>>>(dec_w3, dec_b3, out);

    if (out_size >= 3 * OUTN)
        k_copy_hc<<<(BB * HD * NP2 + 255) / 256, 256>>>(out);
}

// round 7
// speedup vs baseline: 1.4820x; 1.1405x over previous
#include <cuda_runtime.h>
#include <cuda_bf16.h>
#include <math.h>

// ---------------------------------------------------------------------------
//   x: (8,16,3,84,84)  B=8 T=16  -> BT=128 frames
//   enc: 3->64 (pool), 64->128 (pool), 128->256    @84/42/21
//   ConvLSTM: depthwise 3x3 g=512, pointwise 512->1024, gates
//   dec: up2 conv 256->128 @42, up2 conv 128->64 @84, 1x1 64->1
//   All inter-layer buffers use halo-padded channel layouts so smem fills
//   are pure linear float4 copies (no div/mod, no bounds checks).
// ---------------------------------------------------------------------------

#define BT   128
#define BB   8
#define TT   16
#define HD   256
#define NP2  441
#define NP0  7056
#define OUTN 903168

#define E1S  1936   // 44*44 padded channel (42x42 interior)
#define E2S  544    // 23*23=529 padded to 544 (21x21 interior), /4
#define GWS  448    // 441 padded to 448, /4
#define D1S  1936   // 44*44 padded channel (42x42 interior)

__device__ float g_e1p [(size_t)BT * 64  * E1S];
__device__ float g_e2p [(size_t)BT * 128 * E2S];
__device__ float g_feat[(size_t)BT * 256 * NP2];
__device__ float g_gdwf[(size_t)BT * 256 * GWS];
__device__ float g_gdwh[(size_t)BB * 256 * GWS];
__device__ float g_hsp [(size_t)BT * 256 * E2S];
__device__ float g_d1p [(size_t)BT * 128 * D1S];
__device__ float g_d2  [(size_t)BT * 64  * NP0];
__device__ float g_h   [BB * HD * NP2];
__device__ float g_c   [BB * HD * NP2];

__device__ __forceinline__ float sigm(float x) { return 1.0f / (1.0f + expf(-x)); }

// grid-stride float4 zero
__global__ void k_zero(float4* p, int n4)
{
    int i = blockIdx.x * blockDim.x + threadIdx.x;
    int stride = gridDim.x * blockDim.x;
    float4 z = {0.f, 0.f, 0.f, 0.f};
    for (; i < n4; i += stride) p[i] = z;
}

__global__ void k_zero_hc()
{
    int i = blockIdx.x * blockDim.x + threadIdx.x;
    if (i < BB * HD * NP2) { g_h[i] = 0.0f; g_c[i] = 0.0f; }
}

// ---------------------------------------------------------------------------
// enc1: conv3x3 3->64 + bias + relu + maxpool2.  84x84 -> 42x42 into e1p pad.
// ---------------------------------------------------------------------------
__global__ void __launch_bounds__(448) k_enc1(
    const float* __restrict__ x, const float* __restrict__ w,
    const float* __restrict__ bias)
{
    __shared__ float s_in[3 * 44 * 44];
    __shared__ __align__(16) float s_w[3 * 9 * 64];

    const int n   = blockIdx.z;
    const int bx  = blockIdx.x;
    const int py0 = (bx >> 1) * 21;
    const int px0 = (bx & 1) * 21;
    const int oy0 = py0 * 2;
    const int ox0 = px0 * 2;
    const int tid = threadIdx.x;

    const float* xn = x + (size_t)n * 3 * NP0;

    for (int idx = tid; idx < 3 * 44 * 44; idx += 448) {
        int ci = idx / 1936, rem = idx % 1936;
        int r = rem / 44, c = rem % 44;
        int gy = oy0 - 1 + r, gx = ox0 - 1 + c;
        float v = 0.0f;
        if (gy >= 0 && gy < 84 && gx >= 0 && gx < 84)
            v = xn[(size_t)ci * NP0 + gy * 84 + gx];
        s_in[idx] = v;
    }
    for (int idx = tid; idx < 3 * 9 * 64; idx += 448) {
        int ci = idx / (9 * 64); int k = (idx % (9 * 64)) / 64; int co = idx % 64;
        s_w[idx] = w[((size_t)co * 3 + ci) * 9 + k];
    }
    __syncthreads();
    if (tid >= 441) return;

    const int ty = tid / 21, tx = tid % 21;
    const int by = 2 * ty, bxp = 2 * tx;

    for (int cg = 0; cg < 8; cg++) {
        float acc[8][4];
        #pragma unroll
        for (int j = 0; j < 8; j++) { acc[j][0]=acc[j][1]=acc[j][2]=acc[j][3]=0.f; }
        #pragma unroll
        for (int ci = 0; ci < 3; ci++) {
            const float* si = &s_in[ci * 1936];
            #pragma unroll
            for (int k = 0; k < 9; k++) {
                int dy = k / 3, dx = k % 3;
                const float* p0 = si + (by + dy) * 44 + (bxp + dx);
                float v00 = p0[0], v01 = p0[1], v10 = p0[44], v11 = p0[45];
                float4 wA = *(const float4*)&s_w[(ci * 9 + k) * 64 + cg * 8];
                float4 wB = *(const float4*)&s_w[(ci * 9 + k) * 64 + cg * 8 + 4];
                float wv[8] = {wA.x, wA.y, wA.z, wA.w, wB.x, wB.y, wB.z, wB.w};
                #pragma unroll
                for (int j = 0; j < 8; j++) {
                    acc[j][0] += v00 * wv[j];
                    acc[j][1] += v01 * wv[j];
                    acc[j][2] += v10 * wv[j];
                    acc[j][3] += v11 * wv[j];
                }
            }
        }
        #pragma unroll
        for (int j = 0; j < 8; j++) {
            int co = cg * 8 + j;
            float m = fmaxf(fmaxf(acc[j][0], acc[j][1]), fmaxf(acc[j][2], acc[j][3]));
            m = fmaxf(m + bias[co], 0.0f);
            g_e1p[((size_t)n * 64 + co) * E1S + (py0 + ty + 1) * 44 + (px0 + tx + 1)] = m;
        }
    }
}

// ---------------------------------------------------------------------------
// enc2: conv3x3 64->128 + bias + relu + maxpool2 @42 -> 21 into e2p pad.
// Fill = linear float4 copy of full padded channels.
// ---------------------------------------------------------------------------
__global__ void __launch_bounds__(448) k_enc2(
    const float* __restrict__ w, const float* __restrict__ bias)
{
    const int CC = 4;
    __shared__ __align__(16) float s_in[CC * E1S];
    __shared__ __align__(16) float s_w[CC * 9 * 8];

    const int n   = blockIdx.z;
    const int coB = blockIdx.y * 8;
    const int tid = threadIdx.x;
    const int ty = tid / 21, tx = tid % 21;
    const int by = 2 * ty, bxp = 2 * tx;

    float acc[8][4];
    #pragma unroll
    for (int j = 0; j < 8; j++) { acc[j][0]=acc[j][1]=acc[j][2]=acc[j][3]=0.f; }

    for (int cc = 0; cc < 64; cc += CC) {
        const float4* src4 = (const float4*)&g_e1p[((size_t)n * 64 + cc) * E1S];
        float4* dst4 = (float4*)s_in;
        #pragma unroll 1
        for (int idx = tid; idx < CC * (E1S / 4); idx += 448) dst4[idx] = src4[idx];
        for (int idx = tid; idx < CC * 9 * 8; idx += 448) {
            int ci = idx / 72; int k = (idx % 72) / 8; int co = idx % 8;
            s_w[idx] = w[((size_t)(coB + co) * 64 + (cc + ci)) * 9 + k];
        }
        __syncthreads();
        if (tid < 441) {
            #pragma unroll
            for (int ci = 0; ci < CC; ci++) {
                const float* si = &s_in[ci * E1S];
                #pragma unroll
                for (int k = 0; k < 9; k++) {
                    int dy = k / 3, dx = k % 3;
                    const float* p0 = si + (by + dy) * 44 + (bxp + dx);
                    float v00 = p0[0], v01 = p0[1], v10 = p0[44], v11 = p0[45];
                    float4 wA = *(const float4*)&s_w[(ci * 9 + k) * 8];
                    float4 wB = *(const float4*)&s_w[(ci * 9 + k) * 8 + 4];
                    float wv[8] = {wA.x, wA.y, wA.z, wA.w, wB.x, wB.y, wB.z, wB.w};
                    #pragma unroll
                    for (int j = 0; j < 8; j++) {
                        acc[j][0] += v00 * wv[j];
                        acc[j][1] += v01 * wv[j];
                        acc[j][2] += v10 * wv[j];
                        acc[j][3] += v11 * wv[j];
                    }
                }
            }
        }
        __syncthreads();
    }

    if (tid >= 441) return;
    #pragma unroll
    for (int j = 0; j < 8; j++) {
        int co = coB + j;
        float m = fmaxf(fmaxf(acc[j][0], acc[j][1]), fmaxf(acc[j][2], acc[j][3]));
        m = fmaxf(m + bias[co], 0.0f);
        g_e2p[((size_t)n * 128 + co) * E2S + (ty + 1) * 23 + (tx + 1)] = m;
    }
}

// ---------------------------------------------------------------------------
// enc3: conv3x3 128->256 + bias + relu @21x21 (input e2p, linear fill).
// 448 threads, 1 px x 32 couts.
// ---------------------------------------------------------------------------
__global__ void __launch_bounds__(448) k_enc3(
    const float* __restrict__ w, const float* __restrict__ bias)
{
    const int CC = 8;
    __shared__ __align__(16) float s_in[CC * E2S];
    __shared__ __align__(16) float s_w[CC * 9 * 32];

    const int coB = blockIdx.x * 32;
    const int n   = blockIdx.y;
    const int tid = threadIdx.x;
    const int y = tid / 21, x = tid % 21;

    float acc[32];
    #pragma unroll
    for (int j = 0; j < 32; j++) acc[j] = 0.0f;

    for (int cc = 0; cc < 128; cc += CC) {
        const float4* src4 = (const float4*)&g_e2p[((size_t)n * 128 + cc) * E2S];
        float4* dst4 = (float4*)s_in;
        #pragma unroll 1
        for (int idx = tid; idx < CC * (E2S / 4); idx += 448) dst4[idx] = src4[idx];
        for (int idx = tid; idx < CC * 9 * 32; idx += 448) {
            int ci = idx / 288; int k = (idx % 288) / 32; int co = idx % 32;
            s_w[idx] = w[((size_t)(coB + co) * 128 + (cc + ci)) * 9 + k];
        }
        __syncthreads();
        if (tid < 441) {
            #pragma unroll
            for (int ci = 0; ci < CC; ci++) {
                const float* si = &s_in[ci * E2S + y * 23 + x];
                float v[9];
                #pragma unroll
                for (int r = 0; r < 3; r++) {
                    v[r*3+0] = si[r*23+0]; v[r*3+1] = si[r*23+1]; v[r*3+2] = si[r*23+2];
                }
                #pragma unroll
                for (int k = 0; k < 9; k++) {
                    float vv = v[k];
                    const float* wb = &s_w[(ci * 9 + k) * 32];
                    #pragma unroll
                    for (int q = 0; q < 8; q++) {
                        float4 wq = *(const float4*)(wb + q * 4);
                        acc[q*4+0] += vv * wq.x;
                        acc[q*4+1] += vv * wq.y;
                        acc[q*4+2] += vv * wq.z;
                        acc[q*4+3] += vv * wq.w;
                    }
                }
            }
        }
        __syncthreads();
    }

    if (tid >= 441) return;
    #pragma unroll
    for (int j = 0; j < 32; j++) {
        int co = coB + j;
        g_feat[((size_t)n * 256 + co) * NP2 + tid] = fmaxf(acc[j] + bias[co], 0.0f);
    }
}

// ---------------------------------------------------------------------------
// depthwise conv 3x3 — feat half (ch 0..255), ALL frames
// ---------------------------------------------------------------------------
__global__ void __launch_bounds__(448) k_dw_feat(const float* __restrict__ dww)
{
    __shared__ float s[NP2];
    const int ch  = blockIdx.x;
    const int n   = blockIdx.y;
    const int tid = threadIdx.x;

    const float* src = &g_feat[((size_t)n * 256 + ch) * NP2];
    if (tid < NP2) s[tid] = src[tid];
    __syncthreads();
    if (tid >= NP2) return;

    float wr[9];
    #pragma unroll
    for (int k = 0; k < 9; k++) wr[k] = __ldg(&dww[(size_t)ch * 9 + k]);

    int y = tid / 21, x = tid % 21;
    float acc = 0.0f;
    #pragma unroll
    for (int k = 0; k < 9; k++) {
        int iy = y + k / 3 - 1, ix = x + k % 3 - 1;
        if (iy >= 0 && iy < 21 && ix >= 0 && ix < 21)
            acc += s[iy * 21 + ix] * wr[k];
    }
    g_gdwf[((size_t)n * 256 + ch) * GWS + tid] = acc;
}

// depthwise conv — h half (ch 256..511), per step
__global__ void __launch_bounds__(448) k_dw_h(const float* __restrict__ dww)
{
    __shared__ float s[NP2];
    const int ch  = blockIdx.x;
    const int b   = blockIdx.y;
    const int tid = threadIdx.x;

    const float* src = &g_h[((size_t)b * HD + ch) * NP2];
    if (tid < NP2) s[tid] = src[tid];
    __syncthreads();
    if (tid >= NP2) return;

    float wr[9];
    #pragma unroll
    for (int k = 0; k < 9; k++) wr[k] = __ldg(&dww[(size_t)(256 + ch) * 9 + k]);

    int y = tid / 21, x = tid % 21;
    float acc = 0.0f;
    #pragma unroll
    for (int k = 0; k < 9; k++) {
        int iy = y + k / 3 - 1, ix = x + k % 3 - 1;
        if (iy >= 0 && iy < 21 && ix >= 0 && ix < 21)
            acc += s[iy * 21 + ix] * wr[k];
    }
    g_gdwh[((size_t)b * 256 + ch) * GWS + tid] = acc;
}

// ---------------------------------------------------------------------------
// pointwise 1x1 512->1024 + bias + LSTM gates (monolithic K=512).
// Fill = pure linear float4 copy (4 iterations exactly). grid (32, 8).
// ---------------------------------------------------------------------------
__global__ void __launch_bounds__(448) k_pw_gates(
    const float* __restrict__ pww, const float* __restrict__ pwb, int t)
{
    const int CC = 16;
    __shared__ __align__(16) float s_in[CC * GWS];
    __shared__ __align__(16) float s_w[CC * 32];

    const int coB = blockIdx.x * 8;
    const int b   = blockIdx.y;
    const int tid = threadIdx.x;

    float acc[32];
    #pragma unroll
    for (int j = 0; j < 32; j++) acc[j] = 0.0f;

    for (int cc = 0; cc < 512; cc += CC) {
        const float* src = (cc < 256)
            ? &g_gdwf[((size_t)(b * TT + t) * 256 + cc) * GWS]
            : &g_gdwh[((size_t)b * 256 + (cc - 256)) * GWS];
        const float4* src4 = (const float4*)src;
        float4* dst4 = (float4*)s_in;
        #pragma unroll 1
        for (int idx = tid; idx < CC * (GWS / 4); idx += 448) dst4[idx] = src4[idx];
        for (int idx = tid; idx < CC * 32; idx += 448) {
            int ci = idx >> 5, j = idx & 31;
            int gate = j >> 3, co = j & 7;
            s_w[idx] = pww[((size_t)(gate * 256 + coB + co)) * 512 + cc + ci];
        }
        __syncthreads();
        if (tid < NP2) {
            #pragma unroll
            for (int ci = 0; ci < CC; ci++) {
                float v = s_in[ci * GWS + tid];
                const float* fw = &s_w[ci * 32];
                #pragma unroll
                for (int q = 0; q < 8; q++) {
                    float4 wq = *(const float4*)(fw + q * 4);
                    acc[q*4+0] += v * wq.x;
                    acc[q*4+1] += v * wq.y;
                    acc[q*4+2] += v * wq.z;
                    acc[q*4+3] += v * wq.w;
                }
            }
        }
        __syncthreads();
    }

    if (tid >= NP2) return;
    const int n = b * TT + t;
    const int y = tid / 21, x = tid % 21;
    const int padpix = (y + 1) * 23 + (x + 1);
    #pragma unroll
    for (int co = 0; co < 8; co++) {
        int cg = coB + co;
        float iv = sigm(acc[co]       + pwb[cg]);
        float fv = sigm(acc[8 + co]   + pwb[256 + cg]);
        float ov = sigm(acc[16 + co]  + pwb[512 + cg]);
        float gv = tanhf(acc[24 + co] + pwb[768 + cg]);
        size_t off = ((size_t)b * HD + cg) * NP2 + tid;
        float c2 = fv * g_c[off] + iv * gv;
        float h2 = ov * tanhf(c2);
        g_c[off] = c2;
        g_h[off] = h2;
        g_hsp[((size_t)n * 256 + cg) * E2S + padpix] = h2;
    }
}

// ---------------------------------------------------------------------------
// dec1: folded up2+conv3x3 256->128 @21->42, input hsp (linear fill),
// output d1p padded (scalar stores for alignment).
// ---------------------------------------------------------------------------
__global__ void __launch_bounds__(448) k_dec1(
    const float* __restrict__ w, const float* __restrict__ bias)
{
    const int CC = 8;
    __shared__ __align__(16) float s_in[CC * E2S];
    __shared__ __align__(16) float s_fw[CC * 16 * 8];

    const int coB = blockIdx.x * 8;
    const int n   = blockIdx.y;
    const int tid = threadIdx.x;
    const int ty = tid / 21, tx = tid % 21;

    float acc[8][4];
    #pragma unroll
    for (int j = 0; j < 8; j++) { acc[j][0]=acc[j][1]=acc[j][2]=acc[j][3]=0.f; }

    for (int cc = 0; cc < 256; cc += CC) {
        const float4* src4 = (const float4*)&g_hsp[((size_t)n * 256 + cc) * E2S];
        float4* dst4 = (float4*)s_in;
        #pragma unroll 1
        for (int idx = tid; idx < CC * (E2S / 4); idx += 448) dst4[idx] = src4[idx];
        for (int idx = tid; idx < CC * 128; idx += 448) {
            int ci = idx >> 7;
            int pt = (idx >> 3) & 15;
            int co = idx & 7;
            int par = pt >> 2, tap = pt & 3;
            int py = par >> 1, px = par & 1, a = tap >> 1, b = tap & 1;
            const float* wb = &w[((size_t)(coB + co) * 256 + cc + ci) * 9];
            int rlo, rhi, clo, chi;
            if (py == 0) { if (a == 0) { rlo = 0; rhi = 0; } else { rlo = 1; rhi = 2; } }
            else         { if (a == 0) { rlo = 0; rhi = 1; } else { rlo = 2; rhi = 2; } }
            if (px == 0) { if (b == 0) { clo = 0; chi = 0; } else { clo = 1; chi = 2; } }
            else         { if (b == 0) { clo = 0; chi = 1; } else { clo = 2; chi = 2; } }
            float s = 0.0f;
            for (int r = rlo; r <= rhi; r++)
                for (int c = clo; c <= chi; c++)
                    s += wb[r * 3 + c];
            s_fw[idx] = s;
        }
        __syncthreads();
        if (tid < 441) {
            #pragma unroll
            for (int ci = 0; ci < CC; ci++) {
                const float* si = &s_in[ci * E2S + ty * 23 + tx];
                float v[3][3];
                #pragma unroll
                for (int r = 0; r < 3; r++) {
                    v[r][0] = si[r*23+0]; v[r][1] = si[r*23+1]; v[r][2] = si[r*23+2];
                }
                const float* fw = &s_fw[ci * 128];
                #pragma unroll
                for (int par = 0; par < 4; par++) {
                    const int py = par >> 1, px = par & 1;
                    #pragma unroll
                    for (int tap = 0; tap < 4; tap++) {
                        const int a = tap >> 1, b = tap & 1;
                        float vv = v[py + a][px + b];
                        float4 wA = *(const float4*)&fw[(par * 4 + tap) * 8];
                        float4 wB = *(const float4*)&fw[(par * 4 + tap) * 8 + 4];
                        acc[0][par] += vv * wA.x;  acc[1][par] += vv * wA.y;
                        acc[2][par] += vv * wA.z;  acc[3][par] += vv * wA.w;
                        acc[4][par] += vv * wB.x;  acc[5][par] += vv * wB.y;
                        acc[6][par] += vv * wB.z;  acc[7][par] += vv * wB.w;
                    }
                }
            }
        }
        __syncthreads();
    }

    if (tid >= 441) return;
    #pragma unroll
    for (int j = 0; j < 8; j++) {
        int co = coB + j;
        float bv = bias[co];
        #pragma unroll
        for (int py = 0; py < 2; py++) {
            int Y = ty * 2 + py;
            int X = tx * 2;
            float* op = &g_d1p[((size_t)n * 128 + co) * D1S + (Y + 1) * 44 + (X + 1)];
            op[0] = fmaxf(acc[j][py * 2 + 0] + bv, 0.0f);
            op[1] = fmaxf(acc[j][py * 2 + 1] + bv, 0.0f);
        }
    }
}

// ---------------------------------------------------------------------------
// dec2: folded up2+conv3x3 128->64 @42->84, input d1p (full-channel fill).
// grid (4 tiles, 8 co-groups, BT); CC=4 -> 32 chunks.
// ---------------------------------------------------------------------------
__global__ void __launch_bounds__(448) k_dec2(
    const float* __restrict__ w, const float* __restrict__ bias)
{
    const int CC = 4;
    __shared__ __align__(16) float s_in[CC * D1S];
    __shared__ __align__(16) float s_fw[CC * 16 * 8];

    const int n   = blockIdx.z;
    const int coB = blockIdx.y * 8;
    const int tY  = blockIdx.x >> 1;
    const int tX  = blockIdx.x & 1;
    const int y0  = tY * 21, x0 = tX * 21;
    const int tid = threadIdx.x;
    const int ty = tid / 21, tx = tid % 21;

    float acc[8][4];
    #pragma unroll
    for (int j = 0; j < 8; j++) { acc[j][0]=acc[j][1]=acc[j][2]=acc[j][3]=0.f; }

    for (int cc = 0; cc < 128; cc += CC) {
        const float4* src4 = (const float4*)&g_d1p[((size_t)n * 128 + cc) * D1S];
        float4* dst4 = (float4*)s_in;
        #pragma unroll 1
        for (int idx = tid; idx < CC * (D1S / 4); idx += 448) dst4[idx] = src4[idx];
        for (int idx = tid; idx < CC * 128; idx += 448) {
            int ci = idx >> 7;
            int pt = (idx >> 3) & 15;
            int co = idx & 7;
            int par = pt >> 2, tap = pt & 3;
            int py = par >> 1, px = par & 1, a = tap >> 1, b = tap & 1;
            const float* wb = &w[((size_t)(coB + co) * 128 + cc + ci) * 9];
            int rlo, rhi, clo, chi;
            if (py == 0) { if (a == 0) { rlo = 0; rhi = 0; } else { rlo = 1; rhi = 2; } }
            else         { if (a == 0) { rlo = 0; rhi = 1; } else { rlo = 2; rhi = 2; } }
            if (px == 0) { if (b == 0) { clo = 0; chi = 0; } else { clo = 1; chi = 2; } }
            else         { if (b == 0) { clo = 0; chi = 1; } else { clo = 2; chi = 2; } }
            float s = 0.0f;
            for (int r = rlo; r <= rhi; r++)
                for (int c = clo; c <= chi; c++)
                    s += wb[r * 3 + c];
            s_fw[idx] = s;
        }
        __syncthreads();
        if (tid < 441) {
            #pragma unroll
            for (int ci = 0; ci < CC; ci++) {
                const float* si = &s_in[ci * D1S + (y0 + ty) * 44 + (x0 + tx)];
                float v[3][3];
                #pragma unroll
                for (int r = 0; r < 3; r++) {
                    v[r][0] = si[r*44+0]; v[r][1] = si[r*44+1]; v[r][2] = si[r*44+2];
                }
                const float* fw = &s_fw[ci * 128];
                #pragma unroll
                for (int par = 0; par < 4; par++) {
                    const int py = par >> 1, px = par & 1;
                    #pragma unroll
                    for (int tap = 0; tap < 4; tap++) {
                        const int a = tap >> 1, b = tap & 1;
                        float vv = v[py + a][px + b];
                        float4 wA = *(const float4*)&fw[(par * 4 + tap) * 8];
                        float4 wB = *(const float4*)&fw[(par * 4 + tap) * 8 + 4];
                        acc[0][par] += vv * wA.x;  acc[1][par] += vv * wA.y;
                        acc[2][par] += vv * wA.z;  acc[3][par] += vv * wA.w;
                        acc[4][par] += vv * wB.x;  acc[5][par] += vv * wB.y;
                        acc[6][par] += vv * wB.z;  acc[7][par] += vv * wB.w;
                    }
                }
            }
        }
        __syncthreads();
    }

    if (tid >= 441) return;
    #pragma unroll
    for (int j = 0; j < 8; j++) {
        int co = coB + j;
        float bv = bias[co];
        #pragma unroll
        for (int py = 0; py < 2; py++) {
            int Y = (y0 + ty) * 2 + py;
            int X = (x0 + tx) * 2;
            float2 o;
            o.x = fmaxf(acc[j][py * 2 + 0] + bv, 0.0f);
            o.y = fmaxf(acc[j][py * 2 + 1] + bv, 0.0f);
            *(float2*)&g_d2[((size_t)n * 64 + co) * NP0 + Y * 84 + X] = o;
        }
    }
}

// ---------------------------------------------------------------------------
// dec3: 1x1 conv 64->1 + bias.
// ---------------------------------------------------------------------------
__global__ void k_dec3(const float* __restrict__ w, const float* __restrict__ bias,
                       float* __restrict__ out)
{
    __shared__ float s_w[64];
    if (threadIdx.x < 64) s_w[threadIdx.x] = w[threadIdx.x];
    __syncthreads();

    int idx = blockIdx.x * blockDim.x + threadIdx.x;
    if (idx >= OUTN) return;
    int n = idx / NP0, pix = idx % NP0;
    const float* d = &g_d2[(size_t)n * 64 * NP0 + pix];
    float acc = bias[0];
    #pragma unroll
    for (int c = 0; c < 64; c++) acc += d[(size_t)c * NP0] * s_w[c];
    out[idx] = acc;
}

__global__ void k_copy_hc(float* __restrict__ out)
{
    int i = blockIdx.x * blockDim.x + threadIdx.x;
    if (i < BB * HD * NP2) {
        out[OUTN + i]     = g_h[i];
        out[2 * OUTN + i] = g_c[i];
    }
}

// ---------------------------------------------------------------------------
extern "C" void kernel_launch(void* const* d_in, const int* in_sizes, int n_in,
                              void* d_out, int out_size)
{
    const float* x      = (const float*)d_in[0];
    const float* enc_w1 = (const float*)d_in[1];
    const float* enc_b1 = (const float*)d_in[2];
    const float* enc_w2 = (const float*)d_in[3];
    const float* enc_b2 = (const float*)d_in[4];
    const float* enc_w3 = (const float*)d_in[5];
    const float* enc_b3 = (const float*)d_in[6];
    const float* dw_w   = (const float*)d_in[7];
    const float* pw_w   = (const float*)d_in[8];
    const float* pw_b   = (const float*)d_in[9];
    const float* dec_w1 = (const float*)d_in[10];
    const float* dec_b1 = (const float*)d_in[11];
    const float* dec_w2 = (const float*)d_in[12];
    const float* dec_b2 = (const float*)d_in[13];
    const float* dec_w3 = (const float*)d_in[14];
    const float* dec_b3 = (const float*)d_in[15];
    float* out = (float*)d_out;

    float *e1p, *e2p, *hsp, *d1p;
    cudaGetSymbolAddress((void**)&e1p, g_e1p);
    cudaGetSymbolAddress((void**)&e2p, g_e2p);
    cudaGetSymbolAddress((void**)&hsp, g_hsp);
    cudaGetSymbolAddress((void**)&d1p, g_d1p);

    // zero padded buffers (borders must be 0) + h/c
    k_zero<<<2048, 256>>>((float4*)e1p, BT * 64  * E1S / 4);
    k_zero<<<2048, 256>>>((float4*)e2p, BT * 128 * E2S / 4);
    k_zero<<<2048, 256>>>((float4*)hsp, BT * 256 * E2S / 4);
    k_zero<<<2048, 256>>>((float4*)d1p, BT * 128 * D1S / 4);
    k_zero_hc<<<(BB * HD * NP2 + 255) / 256, 256>>>();

    // encoder
    k_enc1<<<dim3(4, 1, BT), 448>>>(x, enc_w1, enc_b1);
    k_enc2<<<dim3(1, 128 / 8, BT), 448>>>(enc_w2, enc_b2);
    k_enc3<<<dim3(256 / 32, BT), 448>>>(enc_w3, enc_b3);

    // depthwise(feat) for all frames (h-independent)
    k_dw_feat<<<dim3(256, BT), 448>>>(dw_w);

    // ConvLSTM over T=16 steps
    for (int t = 0; t < TT; t++) {
        k_dw_h<<<dim3(256, BB), 448>>>(dw_w);
        k_pw_gates<<<dim3(32, BB), 448>>>(pw_w, pw_b, t);
    }

    // decoder (folded nearest-upsample convs)
    k_dec1<<<dim3(128 / 8, BT), 448>>>(dec_w1, dec_b1);
    k_dec2<<<dim3(4, 64 / 8, BT), 448>>>(dec_w2, dec_b2);
    k_dec3<<<(OUTN + 255) / 256, 256>>>(dec_w3, dec_b3, out);

    if (out_size >= 3 * OUTN)
        k_copy_hc<<<(BB * HD * NP2 + 255) / 256, 256>>>(out);
}